// round 1
// baseline (speedup 1.0000x reference)
#include <cuda_runtime.h>
#include <math.h>

#define FULLMASK 0xffffffffu

constexpr int BATCH = 4, L = 2048, DM = 1024, DI = 2048, E2 = 4096;
constexpr int DR = 64, DS = 16, XD = 96; // XD = DR + 2*DS

// ---- scratch (device globals; no runtime allocation) ----
__device__ float g_xz  [(size_t)BATCH * L * E2];   // in-proj output (b,l,4096): x | z
__device__ float g_xc  [(size_t)BATCH * L * DI];   // conv+gate output (b,l,d)
__device__ float g_xdbl[(size_t)BATCH * L * XD];   // dt_low|B|C (b,l,96)
__device__ float g_delta[(size_t)BATCH * L * DI];  // softplus(dt + b_dt)
__device__ float g_y   [(size_t)BATCH * L * DI];   // gated scan output

__device__ __forceinline__ float sigmoidf_(float x) { return 1.f / (1.f + __expf(-x)); }

// =====================================================================
// GEMM (TN): C[M,N] = A[M,K] * B[N,K]^T     (A row-major lda, B row-major ldb)
// Double-buffered SMEM, 128x128 tile, 8x8 per-thread, 256 threads.
// EPI: 0 = plain store, 1 = softplus(v + bias[n])
// Assumes M % BM == 0, N % BN == 0, K % BK == 0, 16B-aligned rows.
// =====================================================================
template<int BM, int BN, int BK, int TM, int TN, int EPI>
__global__ __launch_bounds__((BM/TM)*(BN/TN))
void gemm_tn(const float* __restrict__ A, int lda,
             const float* __restrict__ Bw, int ldb,
             float* __restrict__ C, int ldc,
             int K, const float* __restrict__ bias)
{
    constexpr int NT = (BM/TM) * (BN/TN);
    constexpr int KQ = BK / 4;
    constexpr int AV = BM * KQ;     // float4 loads for A tile
    constexpr int BV = BN * KQ;
    constexpr int AL = (AV + NT - 1) / NT;
    constexpr int BL = (BV + NT - 1) / NT;

    __shared__ float As[2][BK][BM];
    __shared__ float Bs[2][BK][BN];

    const int tid = threadIdx.x;
    const int tr  = tid / (BN/TN);
    const int tc  = tid % (BN/TN);
    const float* Ab = A  + (size_t)blockIdx.y * BM * lda;
    const float* Bb = Bw + (size_t)blockIdx.x * BN * ldb;

    float4 ar[AL], br[BL];

    // ---- prologue: tile 0 ----
    #pragma unroll
    for (int u = 0; u < AL; ++u) { int i = tid + u*NT; if (i < AV) {
        int m = i / KQ, kq = i % KQ;
        ar[u] = *reinterpret_cast<const float4*>(Ab + (size_t)m*lda + kq*4); } }
    #pragma unroll
    for (int u = 0; u < BL; ++u) { int i = tid + u*NT; if (i < BV) {
        int n = i / KQ, kq = i % KQ;
        br[u] = *reinterpret_cast<const float4*>(Bb + (size_t)n*ldb + kq*4); } }
    #pragma unroll
    for (int u = 0; u < AL; ++u) { int i = tid + u*NT; if (i < AV) {
        int m = i / KQ, kq = i % KQ;
        As[0][kq*4+0][m] = ar[u].x; As[0][kq*4+1][m] = ar[u].y;
        As[0][kq*4+2][m] = ar[u].z; As[0][kq*4+3][m] = ar[u].w; } }
    #pragma unroll
    for (int u = 0; u < BL; ++u) { int i = tid + u*NT; if (i < BV) {
        int n = i / KQ, kq = i % KQ;
        Bs[0][kq*4+0][n] = br[u].x; Bs[0][kq*4+1][n] = br[u].y;
        Bs[0][kq*4+2][n] = br[u].z; Bs[0][kq*4+3][n] = br[u].w; } }
    __syncthreads();

    float acc[TM][TN];
    #pragma unroll
    for (int i = 0; i < TM; ++i)
        #pragma unroll
        for (int j = 0; j < TN; ++j) acc[i][j] = 0.f;

    const int nt = K / BK;
    for (int t = 0; t < nt; ++t) {
        const int cur = t & 1;
        if (t + 1 < nt) {
            const int k0 = (t + 1) * BK;
            #pragma unroll
            for (int u = 0; u < AL; ++u) { int i = tid + u*NT; if (i < AV) {
                int m = i / KQ, kq = i % KQ;
                ar[u] = *reinterpret_cast<const float4*>(Ab + (size_t)m*lda + k0 + kq*4); } }
            #pragma unroll
            for (int u = 0; u < BL; ++u) { int i = tid + u*NT; if (i < BV) {
                int n = i / KQ, kq = i % KQ;
                br[u] = *reinterpret_cast<const float4*>(Bb + (size_t)n*ldb + k0 + kq*4); } }
        }
        #pragma unroll
        for (int k = 0; k < BK; ++k) {
            float a[TM], b[TN];
            #pragma unroll
            for (int i = 0; i < TM; ++i) a[i] = As[cur][k][tr*TM + i];
            #pragma unroll
            for (int j = 0; j < TN; ++j) b[j] = Bs[cur][k][tc*TN + j];
            #pragma unroll
            for (int i = 0; i < TM; ++i)
                #pragma unroll
                for (int j = 0; j < TN; ++j)
                    acc[i][j] = fmaf(a[i], b[j], acc[i][j]);
        }
        if (t + 1 < nt) {
            const int nb = cur ^ 1;
            #pragma unroll
            for (int u = 0; u < AL; ++u) { int i = tid + u*NT; if (i < AV) {
                int m = i / KQ, kq = i % KQ;
                As[nb][kq*4+0][m] = ar[u].x; As[nb][kq*4+1][m] = ar[u].y;
                As[nb][kq*4+2][m] = ar[u].z; As[nb][kq*4+3][m] = ar[u].w; } }
            #pragma unroll
            for (int u = 0; u < BL; ++u) { int i = tid + u*NT; if (i < BV) {
                int n = i / KQ, kq = i % KQ;
                Bs[nb][kq*4+0][n] = br[u].x; Bs[nb][kq*4+1][n] = br[u].y;
                Bs[nb][kq*4+2][n] = br[u].z; Bs[nb][kq*4+3][n] = br[u].w; } }
        }
        __syncthreads();
    }

    // ---- epilogue ----
    #pragma unroll
    for (int i = 0; i < TM; ++i) {
        const int m = blockIdx.y * BM + tr*TM + i;
        #pragma unroll
        for (int j = 0; j < TN; ++j) {
            const int n = blockIdx.x * BN + tc*TN + j;
            float v = acc[i][j];
            if (EPI == 1) {
                v += bias[n];
                v = (v > 20.f) ? v : log1pf(__expf(v));   // softplus
            }
            C[(size_t)m * ldc + n] = v;
        }
    }
}

// =====================================================================
// Dual dilated causal depthwise conv (k=4, dil 1 & 2) + silu + softmax gate.
// One thread computes 16 consecutive l positions for one (b,d) channel.
// Reads x from g_xz (cols [0,DI)), writes g_xc.
// =====================================================================
__global__ __launch_bounds__(256)
void conv_kernel(const float* __restrict__ w1, const float* __restrict__ b1,
                 const float* __restrict__ w2, const float* __restrict__ b2,
                 const float* __restrict__ gates)
{
    const int tid = blockIdx.x * blockDim.x + threadIdx.x;   // BATCH*(L/16)*DI threads
    const int d    = tid % DI;
    const int rest = tid / DI;
    const int lc   = rest % (L / 16);
    const int b    = rest / (L / 16);
    const int l0   = lc * 16;

    const float* xp = g_xz + (size_t)b * L * E2 + d;   // x[b,l,d] = xp[l*E2]
    float*       op = g_xc + (size_t)b * L * DI + d;

    const float w10 = w1[d*4+0], w11 = w1[d*4+1], w12 = w1[d*4+2], w13 = w1[d*4+3];
    const float w20 = w2[d*4+0], w21 = w2[d*4+1], w22 = w2[d*4+2], w23 = w2[d*4+3];
    const float b1v = b1[d], b2v = b2[d];
    const float e0 = __expf(gates[0]), e1 = __expf(gates[1]);
    const float gden = 1.f / (e0 + e1);
    const float g0 = e0 * gden, g1 = e1 * gden;

    float xb[22];                    // x[l0-6 .. l0+15]
    #pragma unroll
    for (int i = 0; i < 22; ++i) {
        const int l = l0 - 6 + i;
        xb[i] = (l >= 0) ? xp[(size_t)l * E2] : 0.f;
    }

    #pragma unroll
    for (int i = 0; i < 16; ++i) {
        // current t = l0+i -> buffer index i+6
        const float x0  = xb[i+6], xm1 = xb[i+5], xm2 = xb[i+4];
        const float xm3 = xb[i+3], xm4 = xb[i+2], xm6 = xb[i+0];
        // out[t] = w[3]x[t] + w[2]x[t-dil] + w[1]x[t-2dil] + w[0]x[t-3dil]
        const float c1 = fmaf(w13, x0, fmaf(w12, xm1, fmaf(w11, xm2, fmaf(w10, xm3, b1v))));
        const float c2 = fmaf(w23, x0, fmaf(w22, xm2, fmaf(w21, xm4, fmaf(w20, xm6, b2v))));
        const float s1 = c1 * sigmoidf_(c1);
        const float s2 = c2 * sigmoidf_(c2);
        op[(size_t)(l0 + i) * DI] = fmaf(g0, s1, g1 * s2);
    }
}

// =====================================================================
// Selective scan, fused with +D*x and *silu(z).
// One warp = 2 channels; 16 lanes = 16 states per channel.
// Block = 8 warps = 16 consecutive channels of one batch.
// =====================================================================
__global__ __launch_bounds__(256)
void scan_kernel(const float* __restrict__ A_log, const float* __restrict__ D_param)
{
    const int tid   = threadIdx.x;
    const int warp  = tid >> 5;
    const int lane  = tid & 31;
    const int half  = lane >> 4;      // 0 or 1
    const int n     = lane & 15;      // state index
    const int blk   = blockIdx.x;     // BATCH * (DI/16) blocks
    const int b     = blk / (DI / 16);
    const int dbase = (blk % (DI / 16)) * 16;
    const int d     = dbase + warp * 2 + half;

    const float Acoef = -__expf(A_log[d * DS + n]);
    const float Dv    = D_param[d];

    const float* dl  = g_delta + (size_t)b * L * DI + d;          // [l*DI]
    const float* xcp = g_xc    + (size_t)b * L * DI + d;          // [l*DI]
    const float* Bp  = g_xdbl  + (size_t)b * L * XD + DR + n;     // [l*XD]
    const float* Cp  = Bp + DS;
    const float* zp  = g_xz    + (size_t)b * L * E2 + DI + d;     // [l*E2]
    float*       yp  = g_y     + (size_t)b * L * DI + d;          // [l*DI]

    float h = 0.f;
    #pragma unroll 4
    for (int l = 0; l < L; ++l) {
        const float dlt = dl [(size_t)l * DI];
        const float xv  = xcp[(size_t)l * DI];
        const float Bv  = Bp [(size_t)l * XD];
        const float Cv  = Cp [(size_t)l * XD];
        const float zv  = zp [(size_t)l * E2];

        const float dA = __expf(dlt * Acoef);
        h = fmaf(h, dA, dlt * Bv * xv);

        float v = h * Cv;
        v += __shfl_xor_sync(FULLMASK, v, 1);
        v += __shfl_xor_sync(FULLMASK, v, 2);
        v += __shfl_xor_sync(FULLMASK, v, 4);
        v += __shfl_xor_sync(FULLMASK, v, 8);

        if (n == 0) {
            const float y = fmaf(Dv, xv, v);
            yp[(size_t)l * DI] = y * (zv * sigmoidf_(zv));
        }
    }
}

// =====================================================================
extern "C" void kernel_launch(void* const* d_in, const int* in_sizes, int n_in,
                              void* d_out, int out_size)
{
    const float* hidden     = (const float*)d_in[0];
    const float* W_in       = (const float*)d_in[1];
    const float* conv_w1    = (const float*)d_in[2];
    const float* conv_b1    = (const float*)d_in[3];
    const float* conv_w2    = (const float*)d_in[4];
    const float* conv_b2    = (const float*)d_in[5];
    const float* conv_gates = (const float*)d_in[6];
    const float* W_x        = (const float*)d_in[7];
    const float* W_dt       = (const float*)d_in[8];
    const float* b_dt       = (const float*)d_in[9];
    const float* A_log      = (const float*)d_in[10];
    const float* D_param    = (const float*)d_in[11];
    const float* W_out      = (const float*)d_in[12];
    float*       out        = (float*)d_out;

    float *p_xz, *p_xc, *p_xdbl, *p_delta, *p_y;
    cudaGetSymbolAddress((void**)&p_xz,    g_xz);
    cudaGetSymbolAddress((void**)&p_xc,    g_xc);
    cudaGetSymbolAddress((void**)&p_xdbl,  g_xdbl);
    cudaGetSymbolAddress((void**)&p_delta, g_delta);
    cudaGetSymbolAddress((void**)&p_y,     g_y);

    const int M = BATCH * L;   // 8192

    // 1) in-proj: xz[b,l,e] = hidden[b,l,:] . W_in[e,:]   (M=8192, N=4096, K=1024)
    gemm_tn<128,128,8,8,8,0><<<dim3(E2/128, M/128), 256>>>(
        hidden, DM, W_in, DM, p_xz, E2, DM, nullptr);

    // 2) dual dilated dwconv + silu + gate  -> g_xc
    conv_kernel<<<(BATCH * (L/16) * DI) / 256, 256>>>(
        conv_w1, conv_b1, conv_w2, conv_b2, conv_gates);

    // 3) x_dbl = xc . W_x^T   (M=8192, N=96, K=2048)
    gemm_tn<64,96,8,4,6,0><<<dim3(1, M/64), 256>>>(
        p_xc, DI, W_x, DI, p_xdbl, XD, DI, nullptr);

    // 4) delta = softplus(dt_low . W_dt^T + b_dt)   (M=8192, N=2048, K=64, lda=96)
    gemm_tn<128,128,8,8,8,1><<<dim3(DI/128, M/128), 256>>>(
        p_xdbl, XD, W_dt, DR, p_delta, DI, DR, b_dt);

    // 5) selective scan + D-skip + silu(z) gate -> g_y
    scan_kernel<<<BATCH * (DI/16), 256>>>(A_log, D_param);

    // 6) out-proj: out = y . W_out^T   (M=8192, N=1024, K=2048)
    gemm_tn<128,128,8,8,8,0><<<dim3(DM/128, M/128), 256>>>(
        p_y, DI, W_out, DI, out, DM, DI, nullptr);
}

// round 2
// speedup vs baseline: 1.5651x; 1.5651x over previous
#include <cuda_runtime.h>
#include <math.h>
#include <stdint.h>

#define FULLMASK 0xffffffffu

constexpr int BATCH = 4, L = 2048, DM = 1024, DI = 2048, E2 = 4096;
constexpr int DR = 64, DS = 16, XD = 96; // XD = DR + 2*DS

// ---- scratch (device globals; no runtime allocation) ----
__device__ float g_xz  [(size_t)BATCH * L * E2];   // in-proj output (b,l,4096): x | z
__device__ float g_xc  [(size_t)BATCH * L * DI];   // conv+gate output (b,l,d)
__device__ float g_xdbl[(size_t)BATCH * L * XD];   // dt_low|B|C (b,l,96)
__device__ float g_delta[(size_t)BATCH * L * DI];  // softplus(dt + b_dt)
__device__ float g_y   [(size_t)BATCH * L * DI];   // gated scan output

__device__ __forceinline__ float sigmoidf_(float x) { return 1.f / (1.f + __expf(-x)); }

__device__ __forceinline__ uint32_t f2tf(float f) {
    uint32_t u;
    asm("cvt.rna.tf32.f32 %0, %1;" : "=r"(u) : "f"(f));
    return u;
}

__device__ __forceinline__ void mma_tf32(float c[4], const uint32_t a[4], const uint32_t b[2]) {
    asm volatile(
        "mma.sync.aligned.m16n8k8.row.col.f32.tf32.tf32.f32 "
        "{%0,%1,%2,%3}, {%4,%5,%6,%7}, {%8,%9}, {%0,%1,%2,%3};"
        : "+f"(c[0]), "+f"(c[1]), "+f"(c[2]), "+f"(c[3])
        : "r"(a[0]), "r"(a[1]), "r"(a[2]), "r"(a[3]), "r"(b[0]), "r"(b[1]));
}

// =====================================================================
// Tensor-core GEMM (TN): C[M,N] = A[M,K] * B[N,K]^T, tf32 inputs, fp32 acc.
// Block 128x128x32, 8 warps (2x4), warp tile 64x32 via m16n8k8.
// Single SMEM buffer [128][36] (conflict-free), register prefetch of next tile.
// EPI: 0 = plain, 1 = softplus(v + bias[n]).  GN: guard N (for N=96).
// Requires: M % 128 == 0, K % 32 == 0, rows 16B-aligned, K cols mult of 4.
// =====================================================================
template<int EPI, bool GN>
__global__ __launch_bounds__(256, 1)
void mma_gemm(const float* __restrict__ A, int lda,
              const float* __restrict__ Bw, int ldb,
              float* __restrict__ C, int ldc,
              int K, int N, const float* __restrict__ bias)
{
    constexpr int BM = 128, BN = 128, BK = 32;
    __shared__ uint32_t As[BM * 36];
    __shared__ uint32_t Bs[BN * 36];

    const int tid  = threadIdx.x;
    const int warp = tid >> 5;
    const int lane = tid & 31;
    const int g    = lane >> 2;   // group (0..7)
    const int t4   = lane & 3;    // thread in group (0..3)
    const int mw   = (warp >> 2) * 64;
    const int nw   = (warp & 3) * 32;

    const float* Ab = A  + (size_t)blockIdx.y * BM * lda;
    const float* Bb = Bw + (size_t)blockIdx.x * BN * ldb;
    const int nBase = blockIdx.x * BN;

    int am[4], ak[4];
    #pragma unroll
    for (int u = 0; u < 4; ++u) { int idx = tid + u * 256; am[u] = idx >> 3; ak[u] = idx & 7; }

    float4 av[4], bv[4];

    auto ldTile = [&](int kt) {
        const int k0 = kt * BK;
        #pragma unroll
        for (int u = 0; u < 4; ++u)
            av[u] = *reinterpret_cast<const float4*>(Ab + (size_t)am[u] * lda + k0 + ak[u] * 4);
        #pragma unroll
        for (int u = 0; u < 4; ++u) {
            if (GN && (nBase + am[u] >= N)) bv[u] = make_float4(0.f, 0.f, 0.f, 0.f);
            else bv[u] = *reinterpret_cast<const float4*>(Bb + (size_t)am[u] * ldb + k0 + ak[u] * 4);
        }
    };
    auto stTile = [&]() {
        #pragma unroll
        for (int u = 0; u < 4; ++u) {
            uint4 pa = { f2tf(av[u].x), f2tf(av[u].y), f2tf(av[u].z), f2tf(av[u].w) };
            *reinterpret_cast<uint4*>(&As[am[u] * 36 + ak[u] * 4]) = pa;
            uint4 pb = { f2tf(bv[u].x), f2tf(bv[u].y), f2tf(bv[u].z), f2tf(bv[u].w) };
            *reinterpret_cast<uint4*>(&Bs[am[u] * 36 + ak[u] * 4]) = pb;
        }
    };

    float acc[4][4][4];
    #pragma unroll
    for (int i = 0; i < 4; ++i)
        #pragma unroll
        for (int j = 0; j < 4; ++j)
            #pragma unroll
            for (int r = 0; r < 4; ++r) acc[i][j][r] = 0.f;

    ldTile(0);
    stTile();
    __syncthreads();

    const int nt = K / BK;
    for (int t = 0; t < nt; ++t) {
        if (t + 1 < nt) ldTile(t + 1);

        #pragma unroll
        for (int kk = 0; kk < 4; ++kk) {
            uint32_t af[4][4], bf[4][2];
            #pragma unroll
            for (int i = 0; i < 4; ++i) {
                const int r  = mw + i * 16 + g;
                const int b0 = r * 36 + kk * 8 + t4;
                af[i][0] = As[b0];
                af[i][1] = As[b0 + 8 * 36];
                af[i][2] = As[b0 + 4];
                af[i][3] = As[b0 + 8 * 36 + 4];
            }
            #pragma unroll
            for (int j = 0; j < 4; ++j) {
                const int c  = nw + j * 8 + g;
                const int b0 = c * 36 + kk * 8 + t4;
                bf[j][0] = Bs[b0];
                bf[j][1] = Bs[b0 + 4];
            }
            #pragma unroll
            for (int i = 0; i < 4; ++i)
                #pragma unroll
                for (int j = 0; j < 4; ++j)
                    mma_tf32(acc[i][j], af[i], bf[j]);
        }
        __syncthreads();
        if (t + 1 < nt) {
            stTile();
            __syncthreads();
        }
    }

    // ---- epilogue ----
    #pragma unroll
    for (int i = 0; i < 4; ++i) {
        const int m = blockIdx.y * BM + mw + i * 16 + g;
        #pragma unroll
        for (int j = 0; j < 4; ++j) {
            const int n = nBase + nw + j * 8 + t4 * 2;
            if (GN && n >= N) continue;
            float v0 = acc[i][j][0], v1 = acc[i][j][1];
            float v2 = acc[i][j][2], v3 = acc[i][j][3];
            if (EPI == 1) {
                const float b0v = bias[n], b1v = bias[n + 1];
                v0 += b0v; v1 += b1v; v2 += b0v; v3 += b1v;
                v0 = (v0 > 20.f) ? v0 : log1pf(__expf(v0));
                v1 = (v1 > 20.f) ? v1 : log1pf(__expf(v1));
                v2 = (v2 > 20.f) ? v2 : log1pf(__expf(v2));
                v3 = (v3 > 20.f) ? v3 : log1pf(__expf(v3));
            }
            *reinterpret_cast<float2*>(&C[(size_t)m * ldc + n])       = make_float2(v0, v1);
            *reinterpret_cast<float2*>(&C[(size_t)(m + 8) * ldc + n]) = make_float2(v2, v3);
        }
    }
}

// =====================================================================
// Dual dilated causal depthwise conv (k=4, dil 1 & 2) + silu + softmax gate.
// =====================================================================
__global__ __launch_bounds__(256)
void conv_kernel(const float* __restrict__ w1, const float* __restrict__ b1,
                 const float* __restrict__ w2, const float* __restrict__ b2,
                 const float* __restrict__ gates)
{
    const int tid = blockIdx.x * blockDim.x + threadIdx.x;
    const int d    = tid % DI;
    const int rest = tid / DI;
    const int lc   = rest % (L / 16);
    const int b    = rest / (L / 16);
    const int l0   = lc * 16;

    const float* xp = g_xz + (size_t)b * L * E2 + d;
    float*       op = g_xc + (size_t)b * L * DI + d;

    const float w10 = w1[d*4+0], w11 = w1[d*4+1], w12 = w1[d*4+2], w13 = w1[d*4+3];
    const float w20 = w2[d*4+0], w21 = w2[d*4+1], w22 = w2[d*4+2], w23 = w2[d*4+3];
    const float b1v = b1[d], b2v = b2[d];
    const float e0 = __expf(gates[0]), e1 = __expf(gates[1]);
    const float gden = 1.f / (e0 + e1);
    const float g0 = e0 * gden, g1 = e1 * gden;

    float xb[22];
    #pragma unroll
    for (int i = 0; i < 22; ++i) {
        const int l = l0 - 6 + i;
        xb[i] = (l >= 0) ? xp[(size_t)l * E2] : 0.f;
    }

    #pragma unroll
    for (int i = 0; i < 16; ++i) {
        const float x0  = xb[i+6], xm1 = xb[i+5], xm2 = xb[i+4];
        const float xm3 = xb[i+3], xm4 = xb[i+2], xm6 = xb[i+0];
        const float c1 = fmaf(w13, x0, fmaf(w12, xm1, fmaf(w11, xm2, fmaf(w10, xm3, b1v))));
        const float c2 = fmaf(w23, x0, fmaf(w22, xm2, fmaf(w21, xm4, fmaf(w20, xm6, b2v))));
        const float s1 = c1 * sigmoidf_(c1);
        const float s2 = c2 * sigmoidf_(c2);
        op[(size_t)(l0 + i) * DI] = fmaf(g0, s1, g1 * s2);
    }
}

// =====================================================================
// Selective scan, fused with +D*x and *silu(z).
// One warp = 2 channels; 16 lanes = 16 states per channel.
// =====================================================================
__global__ __launch_bounds__(256)
void scan_kernel(const float* __restrict__ A_log, const float* __restrict__ D_param)
{
    const int tid   = threadIdx.x;
    const int warp  = tid >> 5;
    const int lane  = tid & 31;
    const int half  = lane >> 4;
    const int n     = lane & 15;
    const int blk   = blockIdx.x;
    const int b     = blk / (DI / 16);
    const int dbase = (blk % (DI / 16)) * 16;
    const int d     = dbase + warp * 2 + half;

    const float Acoef = -__expf(A_log[d * DS + n]);
    const float Dv    = D_param[d];

    const float* dl  = g_delta + (size_t)b * L * DI + d;
    const float* xcp = g_xc    + (size_t)b * L * DI + d;
    const float* Bp  = g_xdbl  + (size_t)b * L * XD + DR + n;
    const float* Cp  = Bp + DS;
    const float* zp  = g_xz    + (size_t)b * L * E2 + DI + d;
    float*       yp  = g_y     + (size_t)b * L * DI + d;

    float h = 0.f;
    #pragma unroll 4
    for (int l = 0; l < L; ++l) {
        const float dlt = dl [(size_t)l * DI];
        const float xv  = xcp[(size_t)l * DI];
        const float Bv  = Bp [(size_t)l * XD];
        const float Cv  = Cp [(size_t)l * XD];
        const float zv  = zp [(size_t)l * E2];

        const float dA = __expf(dlt * Acoef);
        h = fmaf(h, dA, dlt * Bv * xv);

        float v = h * Cv;
        v += __shfl_xor_sync(FULLMASK, v, 1);
        v += __shfl_xor_sync(FULLMASK, v, 2);
        v += __shfl_xor_sync(FULLMASK, v, 4);
        v += __shfl_xor_sync(FULLMASK, v, 8);

        if (n == 0) {
            const float y = fmaf(Dv, xv, v);
            yp[(size_t)l * DI] = y * (zv * sigmoidf_(zv));
        }
    }
}

// =====================================================================
extern "C" void kernel_launch(void* const* d_in, const int* in_sizes, int n_in,
                              void* d_out, int out_size)
{
    const float* hidden     = (const float*)d_in[0];
    const float* W_in       = (const float*)d_in[1];
    const float* conv_w1    = (const float*)d_in[2];
    const float* conv_b1    = (const float*)d_in[3];
    const float* conv_w2    = (const float*)d_in[4];
    const float* conv_b2    = (const float*)d_in[5];
    const float* conv_gates = (const float*)d_in[6];
    const float* W_x        = (const float*)d_in[7];
    const float* W_dt       = (const float*)d_in[8];
    const float* b_dt       = (const float*)d_in[9];
    const float* A_log      = (const float*)d_in[10];
    const float* D_param    = (const float*)d_in[11];
    const float* W_out      = (const float*)d_in[12];
    float*       out        = (float*)d_out;

    float *p_xz, *p_xc, *p_xdbl, *p_delta, *p_y;
    cudaGetSymbolAddress((void**)&p_xz,    g_xz);
    cudaGetSymbolAddress((void**)&p_xc,    g_xc);
    cudaGetSymbolAddress((void**)&p_xdbl,  g_xdbl);
    cudaGetSymbolAddress((void**)&p_delta, g_delta);
    cudaGetSymbolAddress((void**)&p_y,     g_y);

    const int M = BATCH * L;   // 8192

    // 1) in-proj: (M=8192, N=4096, K=1024)
    mma_gemm<0, false><<<dim3(E2 / 128, M / 128), 256>>>(
        hidden, DM, W_in, DM, p_xz, E2, DM, E2, nullptr);

    // 2) dual dilated dwconv + silu + gate -> g_xc
    conv_kernel<<<(BATCH * (L / 16) * DI) / 256, 256>>>(
        conv_w1, conv_b1, conv_w2, conv_b2, conv_gates);

    // 3) x_dbl = xc . W_x^T   (M=8192, N=96, K=2048) — N guarded
    mma_gemm<0, true><<<dim3(1, M / 128), 256>>>(
        p_xc, DI, W_x, DI, p_xdbl, XD, DI, XD, nullptr);

    // 4) delta = softplus(dt_low . W_dt^T + b_dt)   (M=8192, N=2048, K=64)
    mma_gemm<1, false><<<dim3(DI / 128, M / 128), 256>>>(
        p_xdbl, XD, W_dt, DR, p_delta, DI, DR, DI, b_dt);

    // 5) selective scan + D-skip + silu(z) gate -> g_y
    scan_kernel<<<BATCH * (DI / 16), 256>>>(A_log, D_param);

    // 6) out-proj: (M=8192, N=1024, K=2048)
    mma_gemm<0, false><<<dim3(DM / 128, M / 128), 256>>>(
        p_y, DI, W_out, DI, out, DM, DI, DM, nullptr);
}

// round 3
// speedup vs baseline: 1.7002x; 1.0864x over previous
#include <cuda_runtime.h>
#include <math.h>
#include <stdint.h>

#define FULLMASK 0xffffffffu

constexpr int BATCH = 4, L = 2048, DM = 1024, DI = 2048, E2 = 4096;
constexpr int DR = 64, DS = 16, XD = 96; // XD = DR + 2*DS

// ---- scratch (device globals; no runtime allocation) ----
__device__ float g_xz   [(size_t)BATCH * L * E2];   // in-proj out (b,l,4096): x | z
__device__ float g_xc   [(size_t)BATCH * L * DI];   // conv out, exact (scan input)
__device__ float g_xc_tf[(size_t)BATCH * L * DI];   // conv out, tf32-rounded (GEMM A)
__device__ float g_xdbl [(size_t)BATCH * L * XD];   // dt_low|B|C, tf32-rounded
__device__ float g_delta[(size_t)BATCH * L * DI];   // softplus(dt + b_dt), exact
__device__ float g_y    [(size_t)BATCH * L * DI];   // gated scan out, tf32-rounded
// tf32-rounded copies of GEMM operands fed via cp.async
__device__ float g_h_tf   [(size_t)BATCH * L * DM];
__device__ float g_win_tf [(size_t)E2 * DM];
__device__ float g_wx_tf  [(size_t)XD * DI];
__device__ float g_wdt_tf [(size_t)DI * DR];
__device__ float g_wout_tf[(size_t)DM * DI];

__device__ __forceinline__ float sigmoidf_(float x) { return 1.f / (1.f + __expf(-x)); }

__device__ __forceinline__ uint32_t f2tf(float f) {
    uint32_t u;
    asm("cvt.rna.tf32.f32 %0, %1;" : "=r"(u) : "f"(f));
    return u;
}
__device__ __forceinline__ float tf32r(float f) { return __uint_as_float(f2tf(f)); }

__device__ __forceinline__ void mma_tf32(float c[4], const uint32_t a[4], const uint32_t b[2]) {
    asm volatile(
        "mma.sync.aligned.m16n8k8.row.col.f32.tf32.tf32.f32 "
        "{%0,%1,%2,%3}, {%4,%5,%6,%7}, {%8,%9}, {%0,%1,%2,%3};"
        : "+f"(c[0]), "+f"(c[1]), "+f"(c[2]), "+f"(c[3])
        : "r"(a[0]), "r"(a[1]), "r"(a[2]), "r"(a[3]), "r"(b[0]), "r"(b[1]));
}

// =====================================================================
// Elementwise tf32 rounding (float4)
// =====================================================================
__global__ __launch_bounds__(256)
void cvt_tf32(const float* __restrict__ in, float* __restrict__ out, int n4)
{
    const int i = blockIdx.x * blockDim.x + threadIdx.x;
    if (i < n4) {
        float4 v = reinterpret_cast<const float4*>(in)[i];
        v.x = tf32r(v.x); v.y = tf32r(v.y); v.z = tf32r(v.z); v.w = tf32r(v.w);
        reinterpret_cast<float4*>(out)[i] = v;
    }
}

// =====================================================================
// Tensor-core GEMM (TN): C[M,N] = A[M,K] * B[N,K]^T, tf32 (pre-rounded f32
// in GMEM), fp32 acc. Block 128x128x32, 8 warps (2x4), warp tile 64x32.
// cp.async 3-stage pipeline + ldmatrix fragment loads.
// EPI: 0 plain, 1 softplus(v+bias[n]), 2 tf32-rounded store. GN: guard N rows.
// Requires M%128==0, K%32==0, rows 16B-aligned.
// =====================================================================
constexpr int GSTG = 128 * 36;            // words per stage (per operand)
constexpr int GSTGB = GSTG * 4;           // bytes
constexpr int GSMEM = 3 * GSTGB * 2;      // total dynamic smem (110592 B)

template<int EPI, bool GN>
__global__ __launch_bounds__(256, 2)
void mma_gemm(const float* __restrict__ A, int lda,
              const float* __restrict__ Bw, int ldb,
              float* __restrict__ C, int ldc,
              int K, int N, const float* __restrict__ bias)
{
    extern __shared__ __align__(16) float dynsm[];
    const uint32_t sbase = (uint32_t)__cvta_generic_to_shared(dynsm);

    const int tid  = threadIdx.x;
    const int warp = tid >> 5;
    const int lane = tid & 31;
    const int g    = lane >> 2;
    const int t4   = lane & 3;
    const int mw   = (warp >> 2) * 64;
    const int nw   = (warp & 3) * 32;

    const float* Ab = A  + (size_t)blockIdx.y * 128 * lda;
    const float* Bb = Bw + (size_t)blockIdx.x * 128 * ldb;
    const int nBase = blockIdx.x * 128;

    // per-thread ldmatrix base offsets (q = which of 4 m8n8 matrices)
    const int q  = lane >> 3;
    const int rr = lane & 7;
    const uint32_t aOff = (uint32_t)(((mw + (q & 1) * 8 + rr) * 36 + (q >> 1) * 4) * 4);
    const uint32_t bOff = (uint32_t)(((nw + (q >> 1) * 8 + rr) * 36 + (q & 1) * 4) * 4);

    // cp.async slots: 4 chunks (16B) per thread per operand
    int cm[4], ck[4];
    #pragma unroll
    for (int u = 0; u < 4; ++u) { int idx = tid + u * 256; cm[u] = idx >> 3; ck[u] = idx & 7; }

    auto loadStage = [&](int t, int buf) {
        const int k0 = t * 32;
        const uint32_t aS = sbase + buf * GSTGB;
        const uint32_t bS = sbase + 3 * GSTGB + buf * GSTGB;
        #pragma unroll
        for (int u = 0; u < 4; ++u) {
            const float* src = Ab + (size_t)cm[u] * lda + k0 + ck[u] * 4;
            uint32_t dst = aS + (uint32_t)((cm[u] * 36 + ck[u] * 4) * 4);
            asm volatile("cp.async.cg.shared.global [%0], [%1], 16;" :: "r"(dst), "l"(src));
        }
        #pragma unroll
        for (int u = 0; u < 4; ++u) {
            uint32_t dst = bS + (uint32_t)((cm[u] * 36 + ck[u] * 4) * 4);
            if (GN) {
                const bool ok = (nBase + cm[u]) < N;
                const float* src = Bb + (size_t)(ok ? cm[u] : 0) * ldb + k0 + ck[u] * 4;
                const int sz = ok ? 16 : 0;
                asm volatile("cp.async.cg.shared.global [%0], [%1], 16, %2;"
                             :: "r"(dst), "l"(src), "r"(sz));
            } else {
                const float* src = Bb + (size_t)cm[u] * ldb + k0 + ck[u] * 4;
                asm volatile("cp.async.cg.shared.global [%0], [%1], 16;" :: "r"(dst), "l"(src));
            }
        }
    };

    float acc[4][4][4];
    #pragma unroll
    for (int i = 0; i < 4; ++i)
        #pragma unroll
        for (int j = 0; j < 4; ++j)
            #pragma unroll
            for (int r = 0; r < 4; ++r) acc[i][j][r] = 0.f;

    const int nt = K / 32;

    if (0 < nt) loadStage(0, 0);
    asm volatile("cp.async.commit_group;");
    if (1 < nt) loadStage(1, 1);
    asm volatile("cp.async.commit_group;");

    for (int t = 0; t < nt; ++t) {
        asm volatile("cp.async.wait_group 1;");
        __syncthreads();
        if (t + 2 < nt) loadStage(t + 2, (t + 2) % 3);
        asm volatile("cp.async.commit_group;");

        const int buf = t % 3;
        const uint32_t aS = sbase + buf * GSTGB + aOff;
        const uint32_t bS = sbase + 3 * GSTGB + buf * GSTGB + bOff;

        #pragma unroll
        for (int kk = 0; kk < 4; ++kk) {
            uint32_t af[4][4], bf[4][2];
            #pragma unroll
            for (int i = 0; i < 4; ++i) {
                asm volatile("ldmatrix.sync.aligned.m8n8.x4.shared.b16 {%0,%1,%2,%3}, [%4];"
                    : "=r"(af[i][0]), "=r"(af[i][1]), "=r"(af[i][2]), "=r"(af[i][3])
                    : "r"(aS + (uint32_t)((i * 16 * 36 + kk * 8) * 4)));
            }
            #pragma unroll
            for (int jj = 0; jj < 2; ++jj) {
                asm volatile("ldmatrix.sync.aligned.m8n8.x4.shared.b16 {%0,%1,%2,%3}, [%4];"
                    : "=r"(bf[2*jj][0]), "=r"(bf[2*jj][1]), "=r"(bf[2*jj+1][0]), "=r"(bf[2*jj+1][1])
                    : "r"(bS + (uint32_t)((jj * 16 * 36 + kk * 8) * 4)));
            }
            #pragma unroll
            for (int i = 0; i < 4; ++i)
                #pragma unroll
                for (int j = 0; j < 4; ++j)
                    mma_tf32(acc[i][j], af[i], bf[j]);
        }
    }

    // ---- epilogue ----
    #pragma unroll
    for (int i = 0; i < 4; ++i) {
        const int m = blockIdx.y * 128 + mw + i * 16 + g;
        #pragma unroll
        for (int j = 0; j < 4; ++j) {
            const int n = nBase + nw + j * 8 + t4 * 2;
            if (GN && n >= N) continue;
            float v0 = acc[i][j][0], v1 = acc[i][j][1];
            float v2 = acc[i][j][2], v3 = acc[i][j][3];
            if (EPI == 1) {
                const float b0v = bias[n], b1v = bias[n + 1];
                v0 += b0v; v1 += b1v; v2 += b0v; v3 += b1v;
                v0 = (v0 > 20.f) ? v0 : log1pf(__expf(v0));
                v1 = (v1 > 20.f) ? v1 : log1pf(__expf(v1));
                v2 = (v2 > 20.f) ? v2 : log1pf(__expf(v2));
                v3 = (v3 > 20.f) ? v3 : log1pf(__expf(v3));
            }
            if (EPI == 2) { v0 = tf32r(v0); v1 = tf32r(v1); v2 = tf32r(v2); v3 = tf32r(v3); }
            *reinterpret_cast<float2*>(&C[(size_t)m * ldc + n])       = make_float2(v0, v1);
            *reinterpret_cast<float2*>(&C[(size_t)(m + 8) * ldc + n]) = make_float2(v2, v3);
        }
    }
}

// =====================================================================
// Dual dilated causal depthwise conv (k=4, dil 1 & 2) + silu + softmax gate.
// Dual store: exact (scan) + tf32-rounded (x_dbl GEMM A operand).
// =====================================================================
__global__ __launch_bounds__(256)
void conv_kernel(const float* __restrict__ w1, const float* __restrict__ b1,
                 const float* __restrict__ w2, const float* __restrict__ b2,
                 const float* __restrict__ gates)
{
    const int tid = blockIdx.x * blockDim.x + threadIdx.x;
    const int d    = tid % DI;
    const int rest = tid / DI;
    const int lc   = rest % (L / 16);
    const int b    = rest / (L / 16);
    const int l0   = lc * 16;

    const float* xp = g_xz + (size_t)b * L * E2 + d;
    const size_t obase = (size_t)b * L * DI + d;

    const float w10 = w1[d*4+0], w11 = w1[d*4+1], w12 = w1[d*4+2], w13 = w1[d*4+3];
    const float w20 = w2[d*4+0], w21 = w2[d*4+1], w22 = w2[d*4+2], w23 = w2[d*4+3];
    const float b1v = b1[d], b2v = b2[d];
    const float e0 = __expf(gates[0]), e1 = __expf(gates[1]);
    const float gden = 1.f / (e0 + e1);
    const float g0 = e0 * gden, g1 = e1 * gden;

    float xb[22];
    #pragma unroll
    for (int i = 0; i < 22; ++i) {
        const int l = l0 - 6 + i;
        xb[i] = (l >= 0) ? xp[(size_t)l * E2] : 0.f;
    }

    #pragma unroll
    for (int i = 0; i < 16; ++i) {
        const float x0  = xb[i+6], xm1 = xb[i+5], xm2 = xb[i+4];
        const float xm3 = xb[i+3], xm4 = xb[i+2], xm6 = xb[i+0];
        const float c1 = fmaf(w13, x0, fmaf(w12, xm1, fmaf(w11, xm2, fmaf(w10, xm3, b1v))));
        const float c2 = fmaf(w23, x0, fmaf(w22, xm2, fmaf(w21, xm4, fmaf(w20, xm6, b2v))));
        const float s1 = c1 * sigmoidf_(c1);
        const float s2 = c2 * sigmoidf_(c2);
        const float v  = fmaf(g0, s1, g1 * s2);
        g_xc   [obase + (size_t)(l0 + i) * DI] = v;
        g_xc_tf[obase + (size_t)(l0 + i) * DI] = tf32r(v);
    }
}

// =====================================================================
// Selective scan, fused with +D*x and *silu(z). Stores tf32-rounded y.
// One warp = 2 channels; 16 lanes = 16 states per channel.
// =====================================================================
__global__ __launch_bounds__(256)
void scan_kernel(const float* __restrict__ A_log, const float* __restrict__ D_param)
{
    const int tid   = threadIdx.x;
    const int warp  = tid >> 5;
    const int lane  = tid & 31;
    const int half  = lane >> 4;
    const int n     = lane & 15;
    const int blk   = blockIdx.x;
    const int b     = blk / (DI / 16);
    const int dbase = (blk % (DI / 16)) * 16;
    const int d     = dbase + warp * 2 + half;

    const float Acoef = -__expf(A_log[d * DS + n]);
    const float Dv    = D_param[d];

    const float* dl  = g_delta + (size_t)b * L * DI + d;
    const float* xcp = g_xc    + (size_t)b * L * DI + d;
    const float* Bp  = g_xdbl  + (size_t)b * L * XD + DR + n;
    const float* Cp  = Bp + DS;
    const float* zp  = g_xz    + (size_t)b * L * E2 + DI + d;
    float*       yp  = g_y     + (size_t)b * L * DI + d;

    float h = 0.f;
    #pragma unroll 4
    for (int l = 0; l < L; ++l) {
        const float dlt = dl [(size_t)l * DI];
        const float xv  = xcp[(size_t)l * DI];
        const float Bv  = Bp [(size_t)l * XD];
        const float Cv  = Cp [(size_t)l * XD];
        const float zv  = zp [(size_t)l * E2];

        const float dA = __expf(dlt * Acoef);
        h = fmaf(h, dA, dlt * Bv * xv);

        float v = h * Cv;
        v += __shfl_xor_sync(FULLMASK, v, 1);
        v += __shfl_xor_sync(FULLMASK, v, 2);
        v += __shfl_xor_sync(FULLMASK, v, 4);
        v += __shfl_xor_sync(FULLMASK, v, 8);

        if (n == 0) {
            const float y = fmaf(Dv, xv, v);
            yp[(size_t)l * DI] = tf32r(y * (zv * sigmoidf_(zv)));
        }
    }
}

// =====================================================================
extern "C" void kernel_launch(void* const* d_in, const int* in_sizes, int n_in,
                              void* d_out, int out_size)
{
    const float* hidden     = (const float*)d_in[0];
    const float* W_in       = (const float*)d_in[1];
    const float* conv_w1    = (const float*)d_in[2];
    const float* conv_b1    = (const float*)d_in[3];
    const float* conv_w2    = (const float*)d_in[4];
    const float* conv_b2    = (const float*)d_in[5];
    const float* conv_gates = (const float*)d_in[6];
    const float* W_x        = (const float*)d_in[7];
    const float* W_dt       = (const float*)d_in[8];
    const float* b_dt       = (const float*)d_in[9];
    const float* A_log      = (const float*)d_in[10];
    const float* D_param    = (const float*)d_in[11];
    const float* W_out      = (const float*)d_in[12];
    float*       out        = (float*)d_out;

    float *p_xz, *p_xctf, *p_xdbl, *p_delta, *p_y;
    float *p_h, *p_win, *p_wx, *p_wdt, *p_wout;
    cudaGetSymbolAddress((void**)&p_xz,    g_xz);
    cudaGetSymbolAddress((void**)&p_xctf,  g_xc_tf);
    cudaGetSymbolAddress((void**)&p_xdbl,  g_xdbl);
    cudaGetSymbolAddress((void**)&p_delta, g_delta);
    cudaGetSymbolAddress((void**)&p_y,     g_y);
    cudaGetSymbolAddress((void**)&p_h,     g_h_tf);
    cudaGetSymbolAddress((void**)&p_win,   g_win_tf);
    cudaGetSymbolAddress((void**)&p_wx,    g_wx_tf);
    cudaGetSymbolAddress((void**)&p_wdt,   g_wdt_tf);
    cudaGetSymbolAddress((void**)&p_wout,  g_wout_tf);

    static bool attr_done = false;
    if (!attr_done) {
        cudaFuncSetAttribute(mma_gemm<0,false>, cudaFuncAttributeMaxDynamicSharedMemorySize, GSMEM);
        cudaFuncSetAttribute(mma_gemm<1,false>, cudaFuncAttributeMaxDynamicSharedMemorySize, GSMEM);
        cudaFuncSetAttribute(mma_gemm<2,true>,  cudaFuncAttributeMaxDynamicSharedMemorySize, GSMEM);
        attr_done = true;
    }

    const int M = BATCH * L;   // 8192

    // 0) tf32 pre-rounding of GEMM operands
    auto cvt = [&](const float* src, float* dst, size_t n) {
        int n4 = (int)(n / 4);
        cvt_tf32<<<(n4 + 255) / 256, 256>>>(src, dst, n4);
    };
    cvt(hidden, p_h,    (size_t)BATCH * L * DM);
    cvt(W_in,   p_win,  (size_t)E2 * DM);
    cvt(W_x,    p_wx,   (size_t)XD * DI);
    cvt(W_dt,   p_wdt,  (size_t)DI * DR);
    cvt(W_out,  p_wout, (size_t)DM * DI);

    // 1) in-proj: (M=8192, N=4096, K=1024)
    mma_gemm<0,false><<<dim3(E2/128, M/128), 256, GSMEM>>>(
        p_h, DM, p_win, DM, p_xz, E2, DM, E2, nullptr);

    // 2) dual dilated dwconv + silu + gate -> g_xc (exact) + g_xc_tf
    conv_kernel<<<(BATCH * (L/16) * DI) / 256, 256>>>(
        conv_w1, conv_b1, conv_w2, conv_b2, conv_gates);

    // 3) x_dbl = xc . W_x^T (M=8192, N=96, K=2048), tf32-rounded store
    mma_gemm<2,true><<<dim3(1, M/128), 256, GSMEM>>>(
        p_xctf, DI, p_wx, DI, p_xdbl, XD, DI, XD, nullptr);

    // 4) delta = softplus(dt_low . W_dt^T + b_dt) (M=8192, N=2048, K=64)
    mma_gemm<1,false><<<dim3(DI/128, M/128), 256, GSMEM>>>(
        p_xdbl, XD, p_wdt, DR, p_delta, DI, DR, DI, b_dt);

    // 5) selective scan + D-skip + silu(z) gate -> g_y (tf32-rounded)
    scan_kernel<<<BATCH * (DI/16), 256>>>(A_log, D_param);

    // 6) out-proj: (M=8192, N=1024, K=2048)
    mma_gemm<0,false><<<dim3(DM/128, M/128), 256, GSMEM>>>(
        p_y, DI, p_wout, DI, out, DM, DI, DM, nullptr);
}

// round 6
// speedup vs baseline: 1.8560x; 1.0916x over previous
#include <cuda_runtime.h>
#include <cuda_fp16.h>
#include <math.h>
#include <stdint.h>

#define FULLMASK 0xffffffffu

constexpr int BATCH = 4, L = 2048, DM = 1024, DI = 2048, E2 = 4096;
constexpr int DR = 64, DS = 16, XD = 96; // XD = DR + 2*DS

// ---- scratch (device globals; no runtime allocation) ----
__device__ float  g_xz   [(size_t)BATCH * L * E2];   // in-proj out (f32): x | z
__device__ float  g_xc   [(size_t)BATCH * L * DI];   // conv out, exact (scan)
__device__ __half g_xc_h [(size_t)BATCH * L * DI];   // conv out fp16 (xdbl GEMM A)
__device__ float  g_xdbl [(size_t)BATCH * L * XD];   // dt_low|B|C f32 (scan B/C)
__device__ __half g_xdblh[(size_t)BATCH * L * XD];   // fp16 copy (dt GEMM A)
__device__ float  g_delta[(size_t)BATCH * L * DI];   // softplus(dt+b_dt) (scan)
__device__ __half g_y_h  [(size_t)BATCH * L * DI];   // gated scan out fp16 (out GEMM A)
// fp16 copies of external operands
__device__ __half g_h_h   [(size_t)BATCH * L * DM];
__device__ __half g_win_h [(size_t)E2 * DM];
__device__ __half g_wx_h  [(size_t)XD * DI];
__device__ __half g_wdt_h [(size_t)DI * DR];
__device__ __half g_wout_h[(size_t)DM * DI];

__device__ __forceinline__ float sigmoidf_(float x) { return 1.f / (1.f + __expf(-x)); }

__device__ __forceinline__ void mma_f16(float c[4], const uint32_t a[4], const uint32_t b[2]) {
    asm volatile(
        "mma.sync.aligned.m16n8k16.row.col.f32.f16.f16.f32 "
        "{%0,%1,%2,%3}, {%4,%5,%6,%7}, {%8,%9}, {%0,%1,%2,%3};"
        : "+f"(c[0]), "+f"(c[1]), "+f"(c[2]), "+f"(c[3])
        : "r"(a[0]), "r"(a[1]), "r"(a[2]), "r"(a[3]), "r"(b[0]), "r"(b[1]));
}

// =====================================================================
// f32 -> f16 conversion (float4 -> 4 halves)
// =====================================================================
__global__ __launch_bounds__(256)
void cvt_f16(const float* __restrict__ in, __half* __restrict__ out, int n4)
{
    const int i = blockIdx.x * blockDim.x + threadIdx.x;
    if (i < n4) {
        float4 v = reinterpret_cast<const float4*>(in)[i];
        __half2 h0 = __floats2half2_rn(v.x, v.y);
        __half2 h1 = __floats2half2_rn(v.z, v.w);
        uint2 pk;
        pk.x = *reinterpret_cast<uint32_t*>(&h0);
        pk.y = *reinterpret_cast<uint32_t*>(&h1);
        reinterpret_cast<uint2*>(out)[i] = pk;
    }
}

// =====================================================================
// fp16 tensor GEMM (TN): C[M,N] = A[M,K]*B[N,K]^T, fp16 in, f32 acc.
// Block 128x128x32, 8 warps (2x4), warp tile 64x32 via m16n8k16.
// 4-stage cp.async pipeline, padded 80B SMEM rows (conflict-free ldmatrix).
// EPI: 0 plain f32, 1 softplus(v+bias[n]) f32, 2 f32 store + fp16 dual-store.
// GN guards B rows (N=96). Requires M%128==0, K%32==0, rows 16B-aligned.
// =====================================================================
constexpr int HROW  = 80;                   // bytes per SMEM row (32 fp16 + pad)
constexpr int HASTG = 128 * HROW;           // 10240 B per operand stage
constexpr int HSTG  = 2 * HASTG;            // 20480 B per stage
constexpr int HSMEM = 4 * HSTG;             // 81920 B

template<int EPI, bool GN>
__global__ __launch_bounds__(256, 2)
void h_gemm(const __half* __restrict__ A, int lda,
            const __half* __restrict__ Bw, int ldb,
            float* __restrict__ C, int ldc,
            int K, int N, const float* __restrict__ bias,
            __half* __restrict__ C2)
{
    extern __shared__ __align__(16) char smraw[];
    const uint32_t sbase = (uint32_t)__cvta_generic_to_shared(smraw);

    const int tid  = threadIdx.x;
    const int warp = tid >> 5;
    const int lane = tid & 31;
    const int g    = lane >> 2;       // 0..7
    const int t4   = lane & 3;        // 0..3
    const int mw   = (warp >> 2) * 64;
    const int nw   = (warp & 3) * 32;

    const __half* Ab = A  + (size_t)blockIdx.y * 128 * lda;
    const __half* Bb = Bw + (size_t)blockIdx.x * 128 * ldb;
    const int nBase = blockIdx.x * 128;
    const int nt = K / 32;

    // ldmatrix per-thread row/col within a 16x16 (or n16 x k16) tile
    const int q  = lane >> 3;         // matrix id 0..3
    const int rr = lane & 7;
    const int lmRow = (q & 1) * 8 + rr;      // row within 16-row group
    const int lmCol = (q >> 1) * 16;         // byte offset within 32B k-half

    // cp.async mapping: 512 chunks of 16B per operand; 2 per thread
    int cr[2], cc[2];
    #pragma unroll
    for (int u = 0; u < 2; ++u) { int idx = tid + u * 256; cr[u] = idx >> 2; cc[u] = idx & 3; }

    auto loadStage = [&](int t, int s) {
        const int k0 = t * 32;
        const uint32_t aS = sbase + s * HSTG;
        const uint32_t bS = aS + HASTG;
        #pragma unroll
        for (int u = 0; u < 2; ++u) {
            const __half* src = Ab + (size_t)cr[u] * lda + k0 + cc[u] * 8;
            uint32_t dst = aS + (uint32_t)(cr[u] * HROW + cc[u] * 16);
            asm volatile("cp.async.cg.shared.global [%0], [%1], 16;" :: "r"(dst), "l"(src));
        }
        #pragma unroll
        for (int u = 0; u < 2; ++u) {
            uint32_t dst = bS + (uint32_t)(cr[u] * HROW + cc[u] * 16);
            if (GN) {
                const bool ok = (nBase + cr[u]) < N;
                const __half* src = Bb + (size_t)(ok ? cr[u] : 0) * ldb + k0 + cc[u] * 8;
                const int sz = ok ? 16 : 0;
                asm volatile("cp.async.cg.shared.global [%0], [%1], 16, %2;"
                             :: "r"(dst), "l"(src), "r"(sz));
            } else {
                const __half* src = Bb + (size_t)cr[u] * ldb + k0 + cc[u] * 8;
                asm volatile("cp.async.cg.shared.global [%0], [%1], 16;" :: "r"(dst), "l"(src));
            }
        }
    };

    float acc[4][4][4];
    #pragma unroll
    for (int i = 0; i < 4; ++i)
        #pragma unroll
        for (int j = 0; j < 4; ++j)
            #pragma unroll
            for (int r = 0; r < 4; ++r) acc[i][j][r] = 0.f;

    // prologue: 3 committed groups
    #pragma unroll
    for (int t = 0; t < 3; ++t) {
        if (t < nt) loadStage(t, t);
        asm volatile("cp.async.commit_group;");
    }

    for (int t = 0; t < nt; ++t) {
        asm volatile("cp.async.wait_group 2;");
        __syncthreads();
        if (t + 3 < nt) loadStage(t + 3, (t + 3) & 3);
        asm volatile("cp.async.commit_group;");

        const int s = t & 3;
        const uint32_t aS = sbase + s * HSTG;
        const uint32_t bS = aS + HASTG;

        #pragma unroll
        for (int kk = 0; kk < 2; ++kk) {
            uint32_t af[4][4], bf[4][2];
            #pragma unroll
            for (int i = 0; i < 4; ++i) {
                const uint32_t ad = aS + (uint32_t)((mw + i * 16 + lmRow) * HROW + kk * 32 + lmCol);
                asm volatile("ldmatrix.sync.aligned.m8n8.x4.shared.b16 {%0,%1,%2,%3}, [%4];"
                    : "=r"(af[i][0]), "=r"(af[i][1]), "=r"(af[i][2]), "=r"(af[i][3])
                    : "r"(ad));
            }
            #pragma unroll
            for (int jj = 0; jj < 2; ++jj) {
                const uint32_t bd = bS + (uint32_t)((nw + jj * 16 + lmRow) * HROW + kk * 32 + lmCol);
                asm volatile("ldmatrix.sync.aligned.m8n8.x4.shared.b16 {%0,%1,%2,%3}, [%4];"
                    : "=r"(bf[2*jj][0]), "=r"(bf[2*jj+1][0]), "=r"(bf[2*jj][1]), "=r"(bf[2*jj+1][1])
                    : "r"(bd));
            }
            #pragma unroll
            for (int i = 0; i < 4; ++i)
                #pragma unroll
                for (int j = 0; j < 4; ++j)
                    mma_f16(acc[i][j], af[i], bf[j]);
        }
    }

    // ---- epilogue ----
    #pragma unroll
    for (int i = 0; i < 4; ++i) {
        const int m = blockIdx.y * 128 + mw + i * 16 + g;
        #pragma unroll
        for (int j = 0; j < 4; ++j) {
            const int n = nBase + nw + j * 8 + t4 * 2;
            if (GN && n + 2 > N) continue;
            float v0 = acc[i][j][0], v1 = acc[i][j][1];
            float v2 = acc[i][j][2], v3 = acc[i][j][3];
            if (EPI == 1) {
                const float b0v = bias[n], b1v = bias[n + 1];
                v0 += b0v; v1 += b1v; v2 += b0v; v3 += b1v;
                v0 = (v0 > 20.f) ? v0 : log1pf(__expf(v0));
                v1 = (v1 > 20.f) ? v1 : log1pf(__expf(v1));
                v2 = (v2 > 20.f) ? v2 : log1pf(__expf(v2));
                v3 = (v3 > 20.f) ? v3 : log1pf(__expf(v3));
            }
            *reinterpret_cast<float2*>(&C[(size_t)m * ldc + n])       = make_float2(v0, v1);
            *reinterpret_cast<float2*>(&C[(size_t)(m + 8) * ldc + n]) = make_float2(v2, v3);
            if (EPI == 2) {
                __half2 h0 = __floats2half2_rn(v0, v1);
                __half2 h1 = __floats2half2_rn(v2, v3);
                *reinterpret_cast<__half2*>(&C2[(size_t)m * ldc + n])       = h0;
                *reinterpret_cast<__half2*>(&C2[(size_t)(m + 8) * ldc + n]) = h1;
            }
        }
    }
}

// =====================================================================
// Dual dilated causal depthwise conv + silu + softmax gate.
// Writes exact f32 (scan input) + fp16 (xdbl GEMM A operand).
// =====================================================================
__global__ __launch_bounds__(256)
void conv_kernel(const float* __restrict__ w1, const float* __restrict__ b1,
                 const float* __restrict__ w2, const float* __restrict__ b2,
                 const float* __restrict__ gates)
{
    const int tid = blockIdx.x * blockDim.x + threadIdx.x;
    const int d    = tid % DI;
    const int rest = tid / DI;
    const int lc   = rest % (L / 16);
    const int b    = rest / (L / 16);
    const int l0   = lc * 16;

    const float* xp = g_xz + (size_t)b * L * E2 + d;
    const size_t obase = (size_t)b * L * DI + d;

    const float w10 = w1[d*4+0], w11 = w1[d*4+1], w12 = w1[d*4+2], w13 = w1[d*4+3];
    const float w20 = w2[d*4+0], w21 = w2[d*4+1], w22 = w2[d*4+2], w23 = w2[d*4+3];
    const float b1v = b1[d], b2v = b2[d];
    const float e0 = __expf(gates[0]), e1 = __expf(gates[1]);
    const float gden = 1.f / (e0 + e1);
    const float g0 = e0 * gden, g1 = e1 * gden;

    float xb[22];
    #pragma unroll
    for (int i = 0; i < 22; ++i) {
        const int l = l0 - 6 + i;
        xb[i] = (l >= 0) ? xp[(size_t)l * E2] : 0.f;
    }
    #pragma unroll
    for (int i = 0; i < 16; ++i) {
        const float x0  = xb[i+6], xm1 = xb[i+5], xm2 = xb[i+4];
        const float xm3 = xb[i+3], xm4 = xb[i+2], xm6 = xb[i+0];
        const float c1 = fmaf(w13, x0, fmaf(w12, xm1, fmaf(w11, xm2, fmaf(w10, xm3, b1v))));
        const float c2 = fmaf(w23, x0, fmaf(w22, xm2, fmaf(w21, xm4, fmaf(w20, xm6, b2v))));
        const float s1 = c1 * sigmoidf_(c1);
        const float s2 = c2 * sigmoidf_(c2);
        const float v  = fmaf(g0, s1, g1 * s2);
        g_xc  [obase + (size_t)(l0 + i) * DI] = v;
        g_xc_h[obase + (size_t)(l0 + i) * DI] = __float2half_rn(v);
    }
}

// =====================================================================
// Selective scan + D-skip + silu(z) gate; fp16 output (out-proj operand).
// One warp = 2 channels; 16 lanes = 16 states per channel.
// =====================================================================
__global__ __launch_bounds__(256)
void scan_kernel(const float* __restrict__ A_log, const float* __restrict__ D_param)
{
    const int tid   = threadIdx.x;
    const int warp  = tid >> 5;
    const int lane  = tid & 31;
    const int half  = lane >> 4;
    const int n     = lane & 15;
    const int blk   = blockIdx.x;
    const int b     = blk / (DI / 16);
    const int dbase = (blk % (DI / 16)) * 16;
    const int d     = dbase + warp * 2 + half;

    const float Acoef = -__expf(A_log[d * DS + n]);
    const float Dv    = D_param[d];

    const float* dl  = g_delta + (size_t)b * L * DI + d;
    const float* xcp = g_xc    + (size_t)b * L * DI + d;
    const float* Bp  = g_xdbl  + (size_t)b * L * XD + DR + n;
    const float* Cp  = Bp + DS;
    const float* zp  = g_xz    + (size_t)b * L * E2 + DI + d;
    __half*      yp  = g_y_h   + (size_t)b * L * DI + d;

    float h = 0.f;
    #pragma unroll 4
    for (int l = 0; l < L; ++l) {
        const float dlt = dl [(size_t)l * DI];
        const float xv  = xcp[(size_t)l * DI];
        const float Bv  = Bp [(size_t)l * XD];
        const float Cv  = Cp [(size_t)l * XD];
        const float zv  = zp [(size_t)l * E2];

        const float dA = __expf(dlt * Acoef);
        h = fmaf(h, dA, dlt * Bv * xv);

        float v = h * Cv;
        v += __shfl_xor_sync(FULLMASK, v, 1);
        v += __shfl_xor_sync(FULLMASK, v, 2);
        v += __shfl_xor_sync(FULLMASK, v, 4);
        v += __shfl_xor_sync(FULLMASK, v, 8);

        if (n == 0) {
            const float y = fmaf(Dv, xv, v);
            yp[(size_t)l * DI] = __float2half_rn(y * (zv * sigmoidf_(zv)));
        }
    }
}

// =====================================================================
extern "C" void kernel_launch(void* const* d_in, const int* in_sizes, int n_in,
                              void* d_out, int out_size)
{
    const float* hidden     = (const float*)d_in[0];
    const float* W_in       = (const float*)d_in[1];
    const float* conv_w1    = (const float*)d_in[2];
    const float* conv_b1    = (const float*)d_in[3];
    const float* conv_w2    = (const float*)d_in[4];
    const float* conv_b2    = (const float*)d_in[5];
    const float* conv_gates = (const float*)d_in[6];
    const float* W_x        = (const float*)d_in[7];
    const float* W_dt       = (const float*)d_in[8];
    const float* b_dt       = (const float*)d_in[9];
    const float* A_log      = (const float*)d_in[10];
    const float* D_param    = (const float*)d_in[11];
    const float* W_out      = (const float*)d_in[12];
    float*       out        = (float*)d_out;

    float  *p_xz, *p_xdbl, *p_delta;
    __half *p_xch, *p_xdblh, *p_yh, *p_h, *p_win, *p_wx, *p_wdt, *p_wout;
    cudaGetSymbolAddress((void**)&p_xz,    g_xz);
    cudaGetSymbolAddress((void**)&p_xdbl,  g_xdbl);
    cudaGetSymbolAddress((void**)&p_delta, g_delta);
    cudaGetSymbolAddress((void**)&p_xch,   g_xc_h);
    cudaGetSymbolAddress((void**)&p_xdblh, g_xdblh);
    cudaGetSymbolAddress((void**)&p_yh,    g_y_h);
    cudaGetSymbolAddress((void**)&p_h,     g_h_h);
    cudaGetSymbolAddress((void**)&p_win,   g_win_h);
    cudaGetSymbolAddress((void**)&p_wx,    g_wx_h);
    cudaGetSymbolAddress((void**)&p_wdt,   g_wdt_h);
    cudaGetSymbolAddress((void**)&p_wout,  g_wout_h);

    static bool attr_done = false;
    if (!attr_done) {
        cudaFuncSetAttribute(h_gemm<0,false>, cudaFuncAttributeMaxDynamicSharedMemorySize, HSMEM);
        cudaFuncSetAttribute(h_gemm<1,false>, cudaFuncAttributeMaxDynamicSharedMemorySize, HSMEM);
        cudaFuncSetAttribute(h_gemm<2,true>,  cudaFuncAttributeMaxDynamicSharedMemorySize, HSMEM);
        attr_done = true;
    }

    const int M = BATCH * L;   // 8192

    // 0) fp16 conversion of external operands
    auto cvt = [&](const float* src, __half* dst, size_t nel) {
        int n4 = (int)(nel / 4);
        cvt_f16<<<(n4 + 255) / 256, 256>>>(src, dst, n4);
    };
    cvt(hidden, p_h,    (size_t)BATCH * L * DM);
    cvt(W_in,   p_win,  (size_t)E2 * DM);
    cvt(W_x,    p_wx,   (size_t)XD * DI);
    cvt(W_dt,   p_wdt,  (size_t)DI * DR);
    cvt(W_out,  p_wout, (size_t)DM * DI);

    // 1) in-proj: (M=8192, N=4096, K=1024) -> g_xz (f32)
    h_gemm<0,false><<<dim3(E2/128, M/128), 256, HSMEM>>>(
        p_h, DM, p_win, DM, p_xz, E2, DM, E2, nullptr, nullptr);

    // 2) dwconv + silu + gate -> g_xc (f32) + g_xc_h (fp16)
    conv_kernel<<<(BATCH * (L/16) * DI) / 256, 256>>>(
        conv_w1, conv_b1, conv_w2, conv_b2, conv_gates);

    // 3) x_dbl: (M=8192, N=96, K=2048) -> g_xdbl (f32) + g_xdblh (fp16)
    h_gemm<2,true><<<dim3(1, M/128), 256, HSMEM>>>(
        p_xch, DI, p_wx, DI, p_xdbl, XD, DI, XD, nullptr, p_xdblh);

    // 4) delta = softplus(dt_low . W_dt^T + b_dt): (M=8192, N=2048, K=64)
    h_gemm<1,false><<<dim3(DI/128, M/128), 256, HSMEM>>>(
        p_xdblh, XD, p_wdt, DR, p_delta, DI, DR, DI, b_dt, nullptr);

    // 5) selective scan -> g_y_h (fp16)
    scan_kernel<<<BATCH * (DI/16), 256>>>(A_log, D_param);

    // 6) out-proj: (M=8192, N=1024, K=2048)
    h_gemm<0,false><<<dim3(DM/128, M/128), 256, HSMEM>>>(
        p_yh, DI, p_wout, DI, out, DM, DI, DM, nullptr, nullptr);
}

// round 7
// speedup vs baseline: 4.5157x; 2.4330x over previous
#include <cuda_runtime.h>
#include <cuda_fp16.h>
#include <math.h>
#include <stdint.h>

#define FULLMASK 0xffffffffu

constexpr int BATCH = 4, L = 2048, DM = 1024, DI = 2048, E2 = 4096;
constexpr int DR = 64, DS = 16, XD = 96; // XD = DR + 2*DS
constexpr int KSPL = 4;                  // split-K factor for x_dbl GEMM

// ---- scratch (device globals; no runtime allocation) ----
__device__ float  g_xz   [(size_t)BATCH * L * E2];   // in-proj out (f32): x | z
__device__ float  g_xc   [(size_t)BATCH * L * DI];   // conv out, exact (scan)
__device__ __half g_xc_h [(size_t)BATCH * L * DI];   // conv out fp16 (xdbl GEMM A)
__device__ float  g_xdbl [(size_t)BATCH * L * XD];   // dt_low|B|C f32 (scan B/C)
__device__ __half g_xdblh[(size_t)BATCH * L * XD];   // fp16 copy (dt GEMM A)
__device__ float  g_xdbl_p[(size_t)KSPL * BATCH * L * XD]; // split-K partials
__device__ float  g_delta[(size_t)BATCH * L * DI];   // softplus(dt+b_dt) (scan)
__device__ __half g_y_h  [(size_t)BATCH * L * DI];   // gated scan out fp16
// fp16 copies of external operands
__device__ __half g_h_h   [(size_t)BATCH * L * DM];
__device__ __half g_win_h [(size_t)E2 * DM];
__device__ __half g_wx_h  [(size_t)XD * DI];
__device__ __half g_wdt_h [(size_t)DI * DR];
__device__ __half g_wout_h[(size_t)DM * DI];

__device__ __forceinline__ float sigmoidf_(float x) { return 1.f / (1.f + __expf(-x)); }

__device__ __forceinline__ void mma_f16(float c[4], const uint32_t a[4], const uint32_t b[2]) {
    asm volatile(
        "mma.sync.aligned.m16n8k16.row.col.f32.f16.f16.f32 "
        "{%0,%1,%2,%3}, {%4,%5,%6,%7}, {%8,%9}, {%0,%1,%2,%3};"
        : "+f"(c[0]), "+f"(c[1]), "+f"(c[2]), "+f"(c[3])
        : "r"(a[0]), "r"(a[1]), "r"(a[2]), "r"(a[3]), "r"(b[0]), "r"(b[1]));
}

__device__ __forceinline__ uint2 cvt4(float4 v) {
    __half2 h0 = __floats2half2_rn(v.x, v.y);
    __half2 h1 = __floats2half2_rn(v.z, v.w);
    uint2 pk;
    pk.x = *reinterpret_cast<uint32_t*>(&h0);
    pk.y = *reinterpret_cast<uint32_t*>(&h1);
    return pk;
}

// =====================================================================
// f32 -> f16 conversion kernels
// =====================================================================
__global__ __launch_bounds__(256)
void cvt_f16(const float* __restrict__ in, __half* __restrict__ out, int n4)
{
    const int i = blockIdx.x * blockDim.x + threadIdx.x;
    if (i < n4)
        reinterpret_cast<uint2*>(out)[i] = cvt4(reinterpret_cast<const float4*>(in)[i]);
}

// fused 3-array conversion (keeps launch count low so in-proj sits at index 3)
__global__ __launch_bounds__(256)
void cvt_f16x3(const float* __restrict__ s0, __half* __restrict__ d0, int n0,
               const float* __restrict__ s1, __half* __restrict__ d1, int n1,
               const float* __restrict__ s2, __half* __restrict__ d2, int n2)
{
    int i = blockIdx.x * blockDim.x + threadIdx.x;
    if (i < n0) {
        reinterpret_cast<uint2*>(d0)[i] = cvt4(reinterpret_cast<const float4*>(s0)[i]);
        return;
    }
    i -= n0;
    if (i < n1) {
        reinterpret_cast<uint2*>(d1)[i] = cvt4(reinterpret_cast<const float4*>(s1)[i]);
        return;
    }
    i -= n1;
    if (i < n2)
        reinterpret_cast<uint2*>(d2)[i] = cvt4(reinterpret_cast<const float4*>(s2)[i]);
}

// =====================================================================
// fp16 tensor GEMM (TN): C[M,N] = A[M,K]*B[N,K]^T, fp16 in, f32 acc.
// Block 128x128x32, 8 warps (2x4), warp tile 64x32 via m16n8k16.
// 4-stage cp.async pipeline, padded 80B SMEM rows (conflict-free ldmatrix).
// EPI: 0 plain f32, 1 softplus(v+bias[n]). GN guards B rows (N=96).
// SPLITK: blockIdx.z selects K-slice and partial-output slab.
// =====================================================================
constexpr int HROW  = 80;
constexpr int HASTG = 128 * HROW;
constexpr int HSTG  = 2 * HASTG;
constexpr int HSMEM = 4 * HSTG;             // 81920 B

template<int EPI, bool GN, bool SPLITK>
__global__ __launch_bounds__(256, 2)
void h_gemm(const __half* __restrict__ A, int lda,
            const __half* __restrict__ Bw, int ldb,
            float* __restrict__ C, int ldc,
            int K, int N, const float* __restrict__ bias)
{
    extern __shared__ __align__(16) char smraw[];
    const uint32_t sbase = (uint32_t)__cvta_generic_to_shared(smraw);

    if (SPLITK) {
        const size_t kz = (size_t)blockIdx.z;
        A  += kz * K;                                   // column offset in A
        Bw += kz * K;                                   // column offset in B
        C  += kz * (size_t)gridDim.y * 128 * ldc;       // partial slab
    }

    const int tid  = threadIdx.x;
    const int warp = tid >> 5;
    const int lane = tid & 31;
    const int g    = lane >> 2;
    const int t4   = lane & 3;
    const int mw   = (warp >> 2) * 64;
    const int nw   = (warp & 3) * 32;

    const __half* Ab = A  + (size_t)blockIdx.y * 128 * lda;
    const __half* Bb = Bw + (size_t)blockIdx.x * 128 * ldb;
    const int nBase = blockIdx.x * 128;
    const int nt = K / 32;

    const int q  = lane >> 3;
    const int rr = lane & 7;
    const int lmRow = (q & 1) * 8 + rr;
    const int lmCol = (q >> 1) * 16;

    int cr[2], cc[2];
    #pragma unroll
    for (int u = 0; u < 2; ++u) { int idx = tid + u * 256; cr[u] = idx >> 2; cc[u] = idx & 3; }

    auto loadStage = [&](int t, int s) {
        const int k0 = t * 32;
        const uint32_t aS = sbase + s * HSTG;
        const uint32_t bS = aS + HASTG;
        #pragma unroll
        for (int u = 0; u < 2; ++u) {
            const __half* src = Ab + (size_t)cr[u] * lda + k0 + cc[u] * 8;
            uint32_t dst = aS + (uint32_t)(cr[u] * HROW + cc[u] * 16);
            asm volatile("cp.async.cg.shared.global [%0], [%1], 16;" :: "r"(dst), "l"(src));
        }
        #pragma unroll
        for (int u = 0; u < 2; ++u) {
            uint32_t dst = bS + (uint32_t)(cr[u] * HROW + cc[u] * 16);
            if (GN) {
                const bool ok = (nBase + cr[u]) < N;
                const __half* src = Bb + (size_t)(ok ? cr[u] : 0) * ldb + k0 + cc[u] * 8;
                const int sz = ok ? 16 : 0;
                asm volatile("cp.async.cg.shared.global [%0], [%1], 16, %2;"
                             :: "r"(dst), "l"(src), "r"(sz));
            } else {
                const __half* src = Bb + (size_t)cr[u] * ldb + k0 + cc[u] * 8;
                asm volatile("cp.async.cg.shared.global [%0], [%1], 16;" :: "r"(dst), "l"(src));
            }
        }
    };

    float acc[4][4][4];
    #pragma unroll
    for (int i = 0; i < 4; ++i)
        #pragma unroll
        for (int j = 0; j < 4; ++j)
            #pragma unroll
            for (int r = 0; r < 4; ++r) acc[i][j][r] = 0.f;

    #pragma unroll
    for (int t = 0; t < 3; ++t) {
        if (t < nt) loadStage(t, t);
        asm volatile("cp.async.commit_group;");
    }

    for (int t = 0; t < nt; ++t) {
        asm volatile("cp.async.wait_group 2;");
        __syncthreads();
        if (t + 3 < nt) loadStage(t + 3, (t + 3) & 3);
        asm volatile("cp.async.commit_group;");

        const int s = t & 3;
        const uint32_t aS = sbase + s * HSTG;
        const uint32_t bS = aS + HASTG;

        #pragma unroll
        for (int kk = 0; kk < 2; ++kk) {
            uint32_t af[4][4], bf[4][2];
            #pragma unroll
            for (int i = 0; i < 4; ++i) {
                const uint32_t ad = aS + (uint32_t)((mw + i * 16 + lmRow) * HROW + kk * 32 + lmCol);
                asm volatile("ldmatrix.sync.aligned.m8n8.x4.shared.b16 {%0,%1,%2,%3}, [%4];"
                    : "=r"(af[i][0]), "=r"(af[i][1]), "=r"(af[i][2]), "=r"(af[i][3])
                    : "r"(ad));
            }
            #pragma unroll
            for (int jj = 0; jj < 2; ++jj) {
                const uint32_t bd = bS + (uint32_t)((nw + jj * 16 + lmRow) * HROW + kk * 32 + lmCol);
                asm volatile("ldmatrix.sync.aligned.m8n8.x4.shared.b16 {%0,%1,%2,%3}, [%4];"
                    : "=r"(bf[2*jj][0]), "=r"(bf[2*jj+1][0]), "=r"(bf[2*jj][1]), "=r"(bf[2*jj+1][1])
                    : "r"(bd));
            }
            #pragma unroll
            for (int i = 0; i < 4; ++i)
                #pragma unroll
                for (int j = 0; j < 4; ++j)
                    mma_f16(acc[i][j], af[i], bf[j]);
        }
    }

    // ---- epilogue ----
    #pragma unroll
    for (int i = 0; i < 4; ++i) {
        const int m = blockIdx.y * 128 + mw + i * 16 + g;
        #pragma unroll
        for (int j = 0; j < 4; ++j) {
            const int n = nBase + nw + j * 8 + t4 * 2;
            if (GN && n + 2 > N) continue;
            float v0 = acc[i][j][0], v1 = acc[i][j][1];
            float v2 = acc[i][j][2], v3 = acc[i][j][3];
            if (EPI == 1) {
                const float b0v = bias[n], b1v = bias[n + 1];
                v0 += b0v; v1 += b1v; v2 += b0v; v3 += b1v;
                v0 = (v0 > 20.f) ? v0 : log1pf(__expf(v0));
                v1 = (v1 > 20.f) ? v1 : log1pf(__expf(v1));
                v2 = (v2 > 20.f) ? v2 : log1pf(__expf(v2));
                v3 = (v3 > 20.f) ? v3 : log1pf(__expf(v3));
            }
            *reinterpret_cast<float2*>(&C[(size_t)m * ldc + n])       = make_float2(v0, v1);
            *reinterpret_cast<float2*>(&C[(size_t)(m + 8) * ldc + n]) = make_float2(v2, v3);
        }
    }
}

// =====================================================================
// split-K reduction for x_dbl: sums KSPL partials -> f32 + fp16
// =====================================================================
__global__ __launch_bounds__(256)
void reduce_xdbl(int n4)
{
    const int i = blockIdx.x * blockDim.x + threadIdx.x;
    if (i >= n4) return;
    const size_t stride4 = (size_t)BATCH * L * XD / 4;
    const float4* p = reinterpret_cast<const float4*>(g_xdbl_p);
    float4 a = p[i], b = p[i + stride4], c = p[i + 2 * stride4], d = p[i + 3 * stride4];
    float4 s;
    s.x = (a.x + b.x) + (c.x + d.x);
    s.y = (a.y + b.y) + (c.y + d.y);
    s.z = (a.z + b.z) + (c.z + d.z);
    s.w = (a.w + b.w) + (c.w + d.w);
    reinterpret_cast<float4*>(g_xdbl)[i] = s;
    reinterpret_cast<uint2*>(g_xdblh)[i] = cvt4(s);
}

// =====================================================================
// Dual dilated causal depthwise conv + silu + softmax gate.
// =====================================================================
__global__ __launch_bounds__(256)
void conv_kernel(const float* __restrict__ w1, const float* __restrict__ b1,
                 const float* __restrict__ w2, const float* __restrict__ b2,
                 const float* __restrict__ gates)
{
    const int tid = blockIdx.x * blockDim.x + threadIdx.x;
    const int d    = tid % DI;
    const int rest = tid / DI;
    const int lc   = rest % (L / 16);
    const int b    = rest / (L / 16);
    const int l0   = lc * 16;

    const float* xp = g_xz + (size_t)b * L * E2 + d;
    const size_t obase = (size_t)b * L * DI + d;

    const float w10 = w1[d*4+0], w11 = w1[d*4+1], w12 = w1[d*4+2], w13 = w1[d*4+3];
    const float w20 = w2[d*4+0], w21 = w2[d*4+1], w22 = w2[d*4+2], w23 = w2[d*4+3];
    const float b1v = b1[d], b2v = b2[d];
    const float e0 = __expf(gates[0]), e1 = __expf(gates[1]);
    const float gden = 1.f / (e0 + e1);
    const float g0 = e0 * gden, g1 = e1 * gden;

    float xb[22];
    #pragma unroll
    for (int i = 0; i < 22; ++i) {
        const int l = l0 - 6 + i;
        xb[i] = (l >= 0) ? xp[(size_t)l * E2] : 0.f;
    }
    #pragma unroll
    for (int i = 0; i < 16; ++i) {
        const float x0  = xb[i+6], xm1 = xb[i+5], xm2 = xb[i+4];
        const float xm3 = xb[i+3], xm4 = xb[i+2], xm6 = xb[i+0];
        const float c1 = fmaf(w13, x0, fmaf(w12, xm1, fmaf(w11, xm2, fmaf(w10, xm3, b1v))));
        const float c2 = fmaf(w23, x0, fmaf(w22, xm2, fmaf(w21, xm4, fmaf(w20, xm6, b2v))));
        const float s1 = c1 * sigmoidf_(c1);
        const float s2 = c2 * sigmoidf_(c2);
        const float v  = fmaf(g0, s1, g1 * s2);
        g_xc  [obase + (size_t)(l0 + i) * DI] = v;
        g_xc_h[obase + (size_t)(l0 + i) * DI] = __float2half_rn(v);
    }
}

// =====================================================================
// Selective scan + D-skip + silu(z) gate, SMEM-staged operands.
// Block = 256 threads = 8 warps = 16 channels of one batch.
// Double-buffered 16-timestep chunks staged cooperatively.
// =====================================================================
constexpr int CH = 16;   // timesteps per chunk
__global__ __launch_bounds__(256)
void scan_kernel(const float* __restrict__ A_log, const float* __restrict__ D_param)
{
    __shared__ float sd [2][CH][16];    // delta
    __shared__ float sxv[2][CH][16];    // xc
    __shared__ float szv[2][CH][16];    // z
    __shared__ float sbc[2][CH][32];    // B | C

    const int tid   = threadIdx.x;
    const int warp  = tid >> 5;
    const int lane  = tid & 31;
    const int half  = lane >> 4;
    const int n     = lane & 15;
    const int ch    = warp * 2 + half;   // channel within block (0..15)
    const int blk   = blockIdx.x;
    const int b     = blk >> 7;          // / (DI/16)
    const int dbase = (blk & 127) * 16;
    const int d     = dbase + ch;

    const float Acoef = -__expf(A_log[d * DS + n]);
    const float Dv    = D_param[d];

    // staging indices: row = timestep-in-chunk, col = channel
    const int srow = tid >> 4;           // 0..15
    const int scol = tid & 15;           // 0..15
    const size_t mb = (size_t)b * L;     // row base (b,l)

    auto stage = [&](int c, int buf) {
        const int l = c * CH + srow;
        sd [buf][srow][scol] = g_delta[(mb + l) * DI + dbase + scol];
        sxv[buf][srow][scol] = g_xc  [(mb + l) * DI + dbase + scol];
        szv[buf][srow][scol] = g_xz  [(mb + l) * E2 + DI + dbase + scol];
        const float2 bc = *reinterpret_cast<const float2*>(
            g_xdbl + (mb + l) * XD + DR + scol * 2);
        sbc[buf][srow][scol * 2]     = bc.x;
        sbc[buf][srow][scol * 2 + 1] = bc.y;
    };

    stage(0, 0);
    __syncthreads();

    __half* yp = g_y_h + mb * DI + d;
    float h = 0.f;

    for (int c = 0; c < L / CH; ++c) {
        const int buf = c & 1;
        if (c + 1 < L / CH) stage(c + 1, buf ^ 1);

        const int lbase = c * CH;
        #pragma unroll
        for (int i = 0; i < CH; ++i) {
            const float dlt = sd [buf][i][ch];
            const float xv  = sxv[buf][i][ch];
            const float zv  = szv[buf][i][ch];
            const float Bv  = sbc[buf][i][n];
            const float Cv  = sbc[buf][i][16 + n];

            const float dA = __expf(dlt * Acoef);
            h = fmaf(h, dA, dlt * Bv * xv);

            float v = h * Cv;
            v += __shfl_xor_sync(FULLMASK, v, 1);
            v += __shfl_xor_sync(FULLMASK, v, 2);
            v += __shfl_xor_sync(FULLMASK, v, 4);
            v += __shfl_xor_sync(FULLMASK, v, 8);

            if (n == 0) {
                const float y = fmaf(Dv, xv, v);
                yp[(size_t)(lbase + i) * DI] = __float2half_rn(y * (zv * sigmoidf_(zv)));
            }
        }
        __syncthreads();
    }
}

// =====================================================================
extern "C" void kernel_launch(void* const* d_in, const int* in_sizes, int n_in,
                              void* d_out, int out_size)
{
    const float* hidden     = (const float*)d_in[0];
    const float* W_in       = (const float*)d_in[1];
    const float* conv_w1    = (const float*)d_in[2];
    const float* conv_b1    = (const float*)d_in[3];
    const float* conv_w2    = (const float*)d_in[4];
    const float* conv_b2    = (const float*)d_in[5];
    const float* conv_gates = (const float*)d_in[6];
    const float* W_x        = (const float*)d_in[7];
    const float* W_dt       = (const float*)d_in[8];
    const float* b_dt       = (const float*)d_in[9];
    const float* A_log      = (const float*)d_in[10];
    const float* D_param    = (const float*)d_in[11];
    const float* W_out      = (const float*)d_in[12];
    float*       out        = (float*)d_out;

    float  *p_xz, *p_xdbl_p, *p_delta;
    __half *p_xch, *p_xdblh, *p_yh, *p_h, *p_win, *p_wx, *p_wdt, *p_wout;
    cudaGetSymbolAddress((void**)&p_xz,     g_xz);
    cudaGetSymbolAddress((void**)&p_xdbl_p, g_xdbl_p);
    cudaGetSymbolAddress((void**)&p_delta,  g_delta);
    cudaGetSymbolAddress((void**)&p_xch,    g_xc_h);
    cudaGetSymbolAddress((void**)&p_xdblh,  g_xdblh);
    cudaGetSymbolAddress((void**)&p_yh,     g_y_h);
    cudaGetSymbolAddress((void**)&p_h,      g_h_h);
    cudaGetSymbolAddress((void**)&p_win,    g_win_h);
    cudaGetSymbolAddress((void**)&p_wx,     g_wx_h);
    cudaGetSymbolAddress((void**)&p_wdt,    g_wdt_h);
    cudaGetSymbolAddress((void**)&p_wout,   g_wout_h);

    static bool attr_done = false;
    if (!attr_done) {
        cudaFuncSetAttribute((const void*)h_gemm<0,false,false>,
                             cudaFuncAttributeMaxDynamicSharedMemorySize, HSMEM);
        cudaFuncSetAttribute((const void*)h_gemm<1,false,false>,
                             cudaFuncAttributeMaxDynamicSharedMemorySize, HSMEM);
        cudaFuncSetAttribute((const void*)h_gemm<0,true,true>,
                             cudaFuncAttributeMaxDynamicSharedMemorySize, HSMEM);
        attr_done = true;
    }

    const int M = BATCH * L;   // 8192

    // [0] cvt hidden, [1] cvt W_in, [2] fused cvt of W_x/W_dt/W_out
    {
        int n4h = (int)((size_t)BATCH * L * DM / 4);
        cvt_f16<<<(n4h + 255) / 256, 256>>>(hidden, p_h, n4h);
        int n4w = (int)((size_t)E2 * DM / 4);
        cvt_f16<<<(n4w + 255) / 256, 256>>>(W_in, p_win, n4w);
        int n0 = (int)((size_t)DM * DI / 4);   // W_out
        int n1 = (int)((size_t)XD * DI / 4);   // W_x
        int n2 = (int)((size_t)DI * DR / 4);   // W_dt
        cvt_f16x3<<<(n0 + n1 + n2 + 255) / 256, 256>>>(
            W_out, p_wout, n0, W_x, p_wx, n1, W_dt, p_wdt, n2);
    }

    // [3] in-proj: (M=8192, N=4096, K=1024)  <-- profiled slot
    h_gemm<0,false,false><<<dim3(E2/128, M/128), 256, HSMEM>>>(
        p_h, DM, p_win, DM, p_xz, E2, DM, E2, nullptr);

    // [4] dwconv + silu + gate -> g_xc (f32) + g_xc_h (fp16)
    conv_kernel<<<(BATCH * (L/16) * DI) / 256, 256>>>(
        conv_w1, conv_b1, conv_w2, conv_b2, conv_gates);

    // [5] x_dbl split-K: (M=8192, N=96, K=2048/4 per slice)
    h_gemm<0,true,true><<<dim3(1, M/128, KSPL), 256, HSMEM>>>(
        p_xch, DI, p_wx, DI, p_xdbl_p, XD, DI / KSPL, XD, nullptr);

    // [6] reduce partials -> g_xdbl (f32) + g_xdblh (fp16)
    {
        int n4 = (int)((size_t)BATCH * L * XD / 4);
        reduce_xdbl<<<(n4 + 255) / 256, 256>>>(n4);
    }

    // [7] delta = softplus(dt_low . W_dt^T + b_dt): (M=8192, N=2048, K=64)
    h_gemm<1,false,false><<<dim3(DI/128, M/128), 256, HSMEM>>>(
        p_xdblh, XD, p_wdt, DR, p_delta, DI, DR, DI, b_dt);

    // [8] selective scan -> g_y_h (fp16)
    scan_kernel<<<BATCH * (DI/16), 256>>>(A_log, D_param);

    // [9] out-proj: (M=8192, N=1024, K=2048)
    h_gemm<0,false,false><<<dim3(DM/128, M/128), 256, HSMEM>>>(
        p_yh, DI, p_wout, DI, out, DM, DI, DM, nullptr);
}

// round 11
// speedup vs baseline: 4.6862x; 1.0378x over previous
#include <cuda_runtime.h>
#include <cuda_fp16.h>
#include <math.h>
#include <stdint.h>

#define FULLMASK 0xffffffffu

constexpr int BATCH = 4, L = 2048, DM = 1024, DI = 2048, E2 = 4096;
constexpr int DR = 64, DS = 16, XD = 96; // XD = DR + 2*DS
constexpr int KSPL = 4;                  // split-K factor for x_dbl GEMM

// ---- scratch (device globals; no runtime allocation) ----
__device__ float  g_xz   [(size_t)BATCH * L * E2];   // in-proj out (f32): x | z
__device__ float  g_xc   [(size_t)BATCH * L * DI];   // conv out, exact (scan)
__device__ __half g_xc_h [(size_t)BATCH * L * DI];   // conv out fp16 (xdbl GEMM A)
__device__ float  g_xdbl [(size_t)BATCH * L * XD];   // dt_low|B|C f32 (scan B/C)
__device__ __half g_xdblh[(size_t)BATCH * L * XD];   // fp16 copy (dt GEMM A)
__device__ float  g_xdbl_p[(size_t)KSPL * BATCH * L * XD]; // split-K partials
__device__ float  g_delta[(size_t)BATCH * L * DI];   // softplus(dt+b_dt) (scan)
__device__ __half g_y_h  [(size_t)BATCH * L * DI];   // gated scan out fp16
// fp16 copies of external operands
__device__ __half g_h_h   [(size_t)BATCH * L * DM];
__device__ __half g_win_h [(size_t)E2 * DM];
__device__ __half g_wx_h  [(size_t)XD * DI];
__device__ __half g_wdt_h [(size_t)DI * DR];
__device__ __half g_wout_h[(size_t)DM * DI];

__device__ __forceinline__ float sigmoidf_(float x) { return 1.f / (1.f + __expf(-x)); }

__device__ __forceinline__ void mma_f16(float c[4], const uint32_t a[4], const uint32_t b[2]) {
    asm volatile(
        "mma.sync.aligned.m16n8k16.row.col.f32.f16.f16.f32 "
        "{%0,%1,%2,%3}, {%4,%5,%6,%7}, {%8,%9}, {%0,%1,%2,%3};"
        : "+f"(c[0]), "+f"(c[1]), "+f"(c[2]), "+f"(c[3])
        : "r"(a[0]), "r"(a[1]), "r"(a[2]), "r"(a[3]), "r"(b[0]), "r"(b[1]));
}

__device__ __forceinline__ uint2 cvt4(float4 v) {
    __half2 h0 = __floats2half2_rn(v.x, v.y);
    __half2 h1 = __floats2half2_rn(v.z, v.w);
    uint2 pk;
    pk.x = *reinterpret_cast<uint32_t*>(&h0);
    pk.y = *reinterpret_cast<uint32_t*>(&h1);
    return pk;
}

// =====================================================================
// f32 -> f16 conversion kernels
// =====================================================================
__global__ __launch_bounds__(256)
void cvt_f16(const float* __restrict__ in, __half* __restrict__ out, int n4)
{
    const int i = blockIdx.x * blockDim.x + threadIdx.x;
    if (i < n4)
        reinterpret_cast<uint2*>(out)[i] = cvt4(reinterpret_cast<const float4*>(in)[i]);
}

__global__ __launch_bounds__(256)
void cvt_f16x3(const float* __restrict__ s0, __half* __restrict__ d0, int n0,
               const float* __restrict__ s1, __half* __restrict__ d1, int n1,
               const float* __restrict__ s2, __half* __restrict__ d2, int n2)
{
    int i = blockIdx.x * blockDim.x + threadIdx.x;
    if (i < n0) {
        reinterpret_cast<uint2*>(d0)[i] = cvt4(reinterpret_cast<const float4*>(s0)[i]);
        return;
    }
    i -= n0;
    if (i < n1) {
        reinterpret_cast<uint2*>(d1)[i] = cvt4(reinterpret_cast<const float4*>(s1)[i]);
        return;
    }
    i -= n1;
    if (i < n2)
        reinterpret_cast<uint2*>(d2)[i] = cvt4(reinterpret_cast<const float4*>(s2)[i]);
}

// =====================================================================
// fp16 tensor GEMM (TN): C[M,N] = A[M,K]*B[N,K]^T, fp16 in, f32 acc.
// Block 128x128x64, 8 warps (2x4), warp tile 64x32 via m16n8k16.
// 3-stage cp.async pipeline (BK=64 -> half the barriers of BK=32),
// padded 144B SMEM rows (conflict-free STS + ldmatrix).
// EPI: 0 plain f32, 1 softplus(v+bias[n]). GN guards B rows (N=96).
// SPLITK: blockIdx.z selects K-slice and partial-output slab.
// =====================================================================
constexpr int HROW  = 144;                  // bytes per SMEM row (64 fp16 + 16 pad)
constexpr int HASTG = 128 * HROW;           // 18432 B per operand stage
constexpr int HSTG  = 2 * HASTG;            // 36864 B per stage
constexpr int HSMEM = 3 * HSTG;             // 110592 B

template<int EPI, bool GN, bool SPLITK>
__global__ __launch_bounds__(256, 2)
void h_gemm(const __half* __restrict__ A, int lda,
            const __half* __restrict__ Bw, int ldb,
            float* __restrict__ C, int ldc,
            int K, int N, const float* __restrict__ bias)
{
    extern __shared__ __align__(16) char smraw[];
    const uint32_t sbase = (uint32_t)__cvta_generic_to_shared(smraw);

    if (SPLITK) {
        const size_t kz = (size_t)blockIdx.z;
        A  += kz * K;
        Bw += kz * K;
        C  += kz * (size_t)gridDim.y * 128 * ldc;
    }

    const int tid  = threadIdx.x;
    const int warp = tid >> 5;
    const int lane = tid & 31;
    const int g    = lane >> 2;
    const int t4   = lane & 3;
    const int mw   = (warp >> 2) * 64;
    const int nw   = (warp & 3) * 32;

    const __half* Ab = A  + (size_t)blockIdx.y * 128 * lda;
    const __half* Bb = Bw + (size_t)blockIdx.x * 128 * ldb;
    const int nBase = blockIdx.x * 128;
    const int nt = K / 64;

    const int q  = lane >> 3;
    const int rr = lane & 7;
    const int lmRow = (q & 1) * 8 + rr;
    const int lmCol = (q >> 1) * 16;

    // cp.async: 1024 16B-chunks per operand; 4 per thread (256 threads)
    int cr[4], cc[4];
    #pragma unroll
    for (int u = 0; u < 4; ++u) { int idx = tid + u * 256; cr[u] = idx >> 3; cc[u] = idx & 7; }

    auto loadStage = [&](int t, int s) {
        const int k0 = t * 64;
        const uint32_t aS = sbase + s * HSTG;
        const uint32_t bS = aS + HASTG;
        #pragma unroll
        for (int u = 0; u < 4; ++u) {
            const __half* src = Ab + (size_t)cr[u] * lda + k0 + cc[u] * 8;
            uint32_t dst = aS + (uint32_t)(cr[u] * HROW + cc[u] * 16);
            asm volatile("cp.async.cg.shared.global [%0], [%1], 16;" :: "r"(dst), "l"(src));
        }
        #pragma unroll
        for (int u = 0; u < 4; ++u) {
            uint32_t dst = bS + (uint32_t)(cr[u] * HROW + cc[u] * 16);
            if (GN) {
                const bool ok = (nBase + cr[u]) < N;
                const __half* src = Bb + (size_t)(ok ? cr[u] : 0) * ldb + k0 + cc[u] * 8;
                const int sz = ok ? 16 : 0;
                asm volatile("cp.async.cg.shared.global [%0], [%1], 16, %2;"
                             :: "r"(dst), "l"(src), "r"(sz));
            } else {
                const __half* src = Bb + (size_t)cr[u] * ldb + k0 + cc[u] * 8;
                asm volatile("cp.async.cg.shared.global [%0], [%1], 16;" :: "r"(dst), "l"(src));
            }
        }
    };

    float acc[4][4][4];
    #pragma unroll
    for (int i = 0; i < 4; ++i)
        #pragma unroll
        for (int j = 0; j < 4; ++j)
            #pragma unroll
            for (int r = 0; r < 4; ++r) acc[i][j][r] = 0.f;

    // prologue: 2 committed groups (3-stage pipeline)
    #pragma unroll
    for (int t = 0; t < 2; ++t) {
        if (t < nt) loadStage(t, t);
        asm volatile("cp.async.commit_group;");
    }

    for (int t = 0; t < nt; ++t) {
        asm volatile("cp.async.wait_group 1;");
        __syncthreads();
        if (t + 2 < nt) loadStage(t + 2, (t + 2) % 3);
        asm volatile("cp.async.commit_group;");

        const int s = t % 3;
        const uint32_t aS = sbase + s * HSTG;
        const uint32_t bS = aS + HASTG;

        #pragma unroll
        for (int kk = 0; kk < 4; ++kk) {
            uint32_t af[4][4], bf[4][2];
            #pragma unroll
            for (int i = 0; i < 4; ++i) {
                const uint32_t ad = aS + (uint32_t)((mw + i * 16 + lmRow) * HROW + kk * 32 + lmCol);
                asm volatile("ldmatrix.sync.aligned.m8n8.x4.shared.b16 {%0,%1,%2,%3}, [%4];"
                    : "=r"(af[i][0]), "=r"(af[i][1]), "=r"(af[i][2]), "=r"(af[i][3])
                    : "r"(ad));
            }
            #pragma unroll
            for (int jj = 0; jj < 2; ++jj) {
                const uint32_t bd = bS + (uint32_t)((nw + jj * 16 + lmRow) * HROW + kk * 32 + lmCol);
                asm volatile("ldmatrix.sync.aligned.m8n8.x4.shared.b16 {%0,%1,%2,%3}, [%4];"
                    : "=r"(bf[2*jj][0]), "=r"(bf[2*jj+1][0]), "=r"(bf[2*jj][1]), "=r"(bf[2*jj+1][1])
                    : "r"(bd));
            }
            #pragma unroll
            for (int i = 0; i < 4; ++i)
                #pragma unroll
                for (int j = 0; j < 4; ++j)
                    mma_f16(acc[i][j], af[i], bf[j]);
        }
    }

    // ---- epilogue ----
    #pragma unroll
    for (int i = 0; i < 4; ++i) {
        const int m = blockIdx.y * 128 + mw + i * 16 + g;
        #pragma unroll
        for (int j = 0; j < 4; ++j) {
            const int n = nBase + nw + j * 8 + t4 * 2;
            if (GN && n + 2 > N) continue;
            float v0 = acc[i][j][0], v1 = acc[i][j][1];
            float v2 = acc[i][j][2], v3 = acc[i][j][3];
            if (EPI == 1) {
                const float b0v = bias[n], b1v = bias[n + 1];
                v0 += b0v; v1 += b1v; v2 += b0v; v3 += b1v;
                v0 = (v0 > 20.f) ? v0 : log1pf(__expf(v0));
                v1 = (v1 > 20.f) ? v1 : log1pf(__expf(v1));
                v2 = (v2 > 20.f) ? v2 : log1pf(__expf(v2));
                v3 = (v3 > 20.f) ? v3 : log1pf(__expf(v3));
            }
            *reinterpret_cast<float2*>(&C[(size_t)m * ldc + n])       = make_float2(v0, v1);
            *reinterpret_cast<float2*>(&C[(size_t)(m + 8) * ldc + n]) = make_float2(v2, v3);
        }
    }
}

// =====================================================================
// split-K reduction for x_dbl: sums KSPL partials -> f32 + fp16
// =====================================================================
__global__ __launch_bounds__(256)
void reduce_xdbl(int n4)
{
    const int i = blockIdx.x * blockDim.x + threadIdx.x;
    if (i >= n4) return;
    const size_t stride4 = (size_t)BATCH * L * XD / 4;
    const float4* p = reinterpret_cast<const float4*>(g_xdbl_p);
    float4 a = p[i], b = p[i + stride4], c = p[i + 2 * stride4], d = p[i + 3 * stride4];
    float4 s;
    s.x = (a.x + b.x) + (c.x + d.x);
    s.y = (a.y + b.y) + (c.y + d.y);
    s.z = (a.z + b.z) + (c.z + d.z);
    s.w = (a.w + b.w) + (c.w + d.w);
    reinterpret_cast<float4*>(g_xdbl)[i] = s;
    reinterpret_cast<uint2*>(g_xdblh)[i] = cvt4(s);
}

// =====================================================================
// Dual dilated causal depthwise conv + silu + softmax gate.
// =====================================================================
__global__ __launch_bounds__(256)
void conv_kernel(const float* __restrict__ w1, const float* __restrict__ b1,
                 const float* __restrict__ w2, const float* __restrict__ b2,
                 const float* __restrict__ gates)
{
    const int tid = blockIdx.x * blockDim.x + threadIdx.x;
    const int d    = tid % DI;
    const int rest = tid / DI;
    const int lc   = rest % (L / 16);
    const int b    = rest / (L / 16);
    const int l0   = lc * 16;

    const float* xp = g_xz + (size_t)b * L * E2 + d;
    const size_t obase = (size_t)b * L * DI + d;

    const float w10 = w1[d*4+0], w11 = w1[d*4+1], w12 = w1[d*4+2], w13 = w1[d*4+3];
    const float w20 = w2[d*4+0], w21 = w2[d*4+1], w22 = w2[d*4+2], w23 = w2[d*4+3];
    const float b1v = b1[d], b2v = b2[d];
    const float e0 = __expf(gates[0]), e1 = __expf(gates[1]);
    const float gden = 1.f / (e0 + e1);
    const float g0 = e0 * gden, g1 = e1 * gden;

    float xb[22];
    #pragma unroll
    for (int i = 0; i < 22; ++i) {
        const int l = l0 - 6 + i;
        xb[i] = (l >= 0) ? xp[(size_t)l * E2] : 0.f;
    }
    #pragma unroll
    for (int i = 0; i < 16; ++i) {
        const float x0  = xb[i+6], xm1 = xb[i+5], xm2 = xb[i+4];
        const float xm3 = xb[i+3], xm4 = xb[i+2], xm6 = xb[i+0];
        const float c1 = fmaf(w13, x0, fmaf(w12, xm1, fmaf(w11, xm2, fmaf(w10, xm3, b1v))));
        const float c2 = fmaf(w23, x0, fmaf(w22, xm2, fmaf(w21, xm4, fmaf(w20, xm6, b2v))));
        const float s1 = c1 * sigmoidf_(c1);
        const float s2 = c2 * sigmoidf_(c2);
        const float v  = fmaf(g0, s1, g1 * s2);
        g_xc  [obase + (size_t)(l0 + i) * DI] = v;
        g_xc_h[obase + (size_t)(l0 + i) * DI] = __float2half_rn(v);
    }
}

// =====================================================================
// Selective scan + D-skip + silu(z) gate, SMEM-staged operands.
// Block = 256 threads = 8 warps = 16 channels of one batch.
// Double-buffered 16-timestep chunks staged cooperatively.
// =====================================================================
constexpr int CH = 16;   // timesteps per chunk
__global__ __launch_bounds__(256)
void scan_kernel(const float* __restrict__ A_log, const float* __restrict__ D_param)
{
    __shared__ float sd [2][CH][16];    // delta
    __shared__ float sxv[2][CH][16];    // xc
    __shared__ float szv[2][CH][16];    // z
    __shared__ float sbc[2][CH][32];    // B | C

    const int tid   = threadIdx.x;
    const int warp  = tid >> 5;
    const int lane  = tid & 31;
    const int half  = lane >> 4;
    const int n     = lane & 15;
    const int ch    = warp * 2 + half;   // channel within block (0..15)
    const int blk   = blockIdx.x;
    const int b     = blk >> 7;          // / (DI/16)
    const int dbase = (blk & 127) * 16;
    const int d     = dbase + ch;

    const float Acoef = -__expf(A_log[d * DS + n]);
    const float Dv    = D_param[d];

    const int srow = tid >> 4;           // 0..15
    const int scol = tid & 15;           // 0..15
    const size_t mb = (size_t)b * L;     // row base (b,l)

    auto stage = [&](int c, int buf) {
        const int l = c * CH + srow;
        sd [buf][srow][scol] = g_delta[(mb + l) * DI + dbase + scol];
        sxv[buf][srow][scol] = g_xc  [(mb + l) * DI + dbase + scol];
        szv[buf][srow][scol] = g_xz  [(mb + l) * E2 + DI + dbase + scol];
        const float2 bc = *reinterpret_cast<const float2*>(
            g_xdbl + (mb + l) * XD + DR + scol * 2);
        sbc[buf][srow][scol * 2]     = bc.x;
        sbc[buf][srow][scol * 2 + 1] = bc.y;
    };

    stage(0, 0);
    __syncthreads();

    __half* yp = g_y_h + mb * DI + d;
    float h = 0.f;

    for (int c = 0; c < L / CH; ++c) {
        const int buf = c & 1;
        if (c + 1 < L / CH) stage(c + 1, buf ^ 1);

        const int lbase = c * CH;
        #pragma unroll
        for (int i = 0; i < CH; ++i) {
            const float dlt = sd [buf][i][ch];
            const float xv  = sxv[buf][i][ch];
            const float zv  = szv[buf][i][ch];
            const float Bv  = sbc[buf][i][n];
            const float Cv  = sbc[buf][i][16 + n];

            const float dA = __expf(dlt * Acoef);
            h = fmaf(h, dA, dlt * Bv * xv);

            float v = h * Cv;
            v += __shfl_xor_sync(FULLMASK, v, 1);
            v += __shfl_xor_sync(FULLMASK, v, 2);
            v += __shfl_xor_sync(FULLMASK, v, 4);
            v += __shfl_xor_sync(FULLMASK, v, 8);

            if (n == 0) {
                const float y = fmaf(Dv, xv, v);
                yp[(size_t)(lbase + i) * DI] = __float2half_rn(y * (zv * sigmoidf_(zv)));
            }
        }
        __syncthreads();
    }
}

// =====================================================================
extern "C" void kernel_launch(void* const* d_in, const int* in_sizes, int n_in,
                              void* d_out, int out_size)
{
    const float* hidden     = (const float*)d_in[0];
    const float* W_in       = (const float*)d_in[1];
    const float* conv_w1    = (const float*)d_in[2];
    const float* conv_b1    = (const float*)d_in[3];
    const float* conv_w2    = (const float*)d_in[4];
    const float* conv_b2    = (const float*)d_in[5];
    const float* conv_gates = (const float*)d_in[6];
    const float* W_x        = (const float*)d_in[7];
    const float* W_dt       = (const float*)d_in[8];
    const float* b_dt       = (const float*)d_in[9];
    const float* A_log      = (const float*)d_in[10];
    const float* D_param    = (const float*)d_in[11];
    const float* W_out      = (const float*)d_in[12];
    float*       out        = (float*)d_out;

    float  *p_xz, *p_xdbl_p, *p_delta;
    __half *p_xch, *p_xdblh, *p_yh, *p_h, *p_win, *p_wx, *p_wdt, *p_wout;
    cudaGetSymbolAddress((void**)&p_xz,     g_xz);
    cudaGetSymbolAddress((void**)&p_xdbl_p, g_xdbl_p);
    cudaGetSymbolAddress((void**)&p_delta,  g_delta);
    cudaGetSymbolAddress((void**)&p_xch,    g_xc_h);
    cudaGetSymbolAddress((void**)&p_xdblh,  g_xdblh);
    cudaGetSymbolAddress((void**)&p_yh,     g_y_h);
    cudaGetSymbolAddress((void**)&p_h,      g_h_h);
    cudaGetSymbolAddress((void**)&p_win,    g_win_h);
    cudaGetSymbolAddress((void**)&p_wx,     g_wx_h);
    cudaGetSymbolAddress((void**)&p_wdt,    g_wdt_h);
    cudaGetSymbolAddress((void**)&p_wout,   g_wout_h);

    static bool attr_done = false;
    if (!attr_done) {
        cudaFuncSetAttribute((const void*)h_gemm<0,false,false>,
                             cudaFuncAttributeMaxDynamicSharedMemorySize, HSMEM);
        cudaFuncSetAttribute((const void*)h_gemm<1,false,false>,
                             cudaFuncAttributeMaxDynamicSharedMemorySize, HSMEM);
        cudaFuncSetAttribute((const void*)h_gemm<0,true,true>,
                             cudaFuncAttributeMaxDynamicSharedMemorySize, HSMEM);
        attr_done = true;
    }

    const int M = BATCH * L;   // 8192

    // [0] cvt hidden, [1] cvt W_in, [2] fused cvt of W_out/W_x/W_dt
    {
        int n4h = (int)((size_t)BATCH * L * DM / 4);
        cvt_f16<<<(n4h + 255) / 256, 256>>>(hidden, p_h, n4h);
        int n4w = (int)((size_t)E2 * DM / 4);
        cvt_f16<<<(n4w + 255) / 256, 256>>>(W_in, p_win, n4w);
        int n0 = (int)((size_t)DM * DI / 4);
        int n1 = (int)((size_t)XD * DI / 4);
        int n2 = (int)((size_t)DI * DR / 4);
        cvt_f16x3<<<(n0 + n1 + n2 + 255) / 256, 256>>>(
            W_out, p_wout, n0, W_x, p_wx, n1, W_dt, p_wdt, n2);
    }

    // [3] in-proj: (M=8192, N=4096, K=1024)
    h_gemm<0,false,false><<<dim3(E2/128, M/128), 256, HSMEM>>>(
        p_h, DM, p_win, DM, p_xz, E2, DM, E2, nullptr);

    // [4] dwconv + silu + gate -> g_xc (f32) + g_xc_h (fp16)
    conv_kernel<<<(BATCH * (L/16) * DI) / 256, 256>>>(
        conv_w1, conv_b1, conv_w2, conv_b2, conv_gates);

    // [5] x_dbl split-K: (M=8192, N=96, K=2048/4 per slice)
    h_gemm<0,true,true><<<dim3(1, M/128, KSPL), 256, HSMEM>>>(
        p_xch, DI, p_wx, DI, p_xdbl_p, XD, DI / KSPL, XD, nullptr);

    // [6] reduce partials -> g_xdbl (f32) + g_xdblh (fp16)
    {
        int n4 = (int)((size_t)BATCH * L * XD / 4);
        reduce_xdbl<<<(n4 + 255) / 256, 256>>>(n4);
    }

    // [7] delta = softplus(dt_low . W_dt^T + b_dt): (M=8192, N=2048, K=64)
    h_gemm<1,false,false><<<dim3(DI/128, M/128), 256, HSMEM>>>(
        p_xdblh, XD, p_wdt, DR, p_delta, DI, DR, DI, b_dt);

    // [8] selective scan -> g_y_h (fp16)
    scan_kernel<<<BATCH * (DI/16), 256>>>(A_log, D_param);

    // [9] out-proj: (M=8192, N=1024, K=2048)
    h_gemm<0,false,false><<<dim3(DM/128, M/128), 256, HSMEM>>>(
        p_yh, DI, p_wout, DI, out, DM, DI, DM, nullptr);
}

// round 13
// speedup vs baseline: 5.1177x; 1.0921x over previous
#include <cuda_runtime.h>
#include <cuda_fp16.h>
#include <math.h>
#include <stdint.h>

#define FULLMASK 0xffffffffu

constexpr int BATCH = 4, L = 2048, DM = 1024, DI = 2048, E2 = 4096;
constexpr int DR = 64, DS = 16, XD = 96; // XD = DR + 2*DS
constexpr int KSPL = 4;                  // split-K factor for x_dbl GEMM

// ---- scratch (device globals; no runtime allocation) ----
__device__ float  g_xz   [(size_t)BATCH * L * E2];   // in-proj out (f32): x | z
__device__ float  g_xc   [(size_t)BATCH * L * DI];   // conv out, exact (scan)
__device__ __half g_xc_h [(size_t)BATCH * L * DI];   // conv out fp16 (xdbl GEMM A)
__device__ float  g_xdbl [(size_t)BATCH * L * XD];   // dt_low|B|C f32 (scan B/C)
__device__ __half g_xdblh[(size_t)BATCH * L * XD];   // fp16 copy (dt GEMM A)
__device__ float  g_xdbl_p[(size_t)KSPL * BATCH * L * XD]; // split-K partials
__device__ float  g_delta[(size_t)BATCH * L * DI];   // softplus(dt+b_dt) (scan)
__device__ __half g_y_h  [(size_t)BATCH * L * DI];   // gated scan out fp16
// fp16 copies of external operands
__device__ __half g_h_h   [(size_t)BATCH * L * DM];
__device__ __half g_win_h [(size_t)E2 * DM];
__device__ __half g_wx_h  [(size_t)XD * DI];
__device__ __half g_wdt_h [(size_t)DI * DR];
__device__ __half g_wout_h[(size_t)DM * DI];

__device__ __forceinline__ float sigmoidf_(float x) { return 1.f / (1.f + __expf(-x)); }

__device__ __forceinline__ float ex2_(float x) {
    float r; asm("ex2.approx.f32 %0, %1;" : "=f"(r) : "f"(x)); return r;
}

__device__ __forceinline__ void mma_f16(float c[4], const uint32_t a[4], const uint32_t b[2]) {
    asm volatile(
        "mma.sync.aligned.m16n8k16.row.col.f32.f16.f16.f32 "
        "{%0,%1,%2,%3}, {%4,%5,%6,%7}, {%8,%9}, {%0,%1,%2,%3};"
        : "+f"(c[0]), "+f"(c[1]), "+f"(c[2]), "+f"(c[3])
        : "r"(a[0]), "r"(a[1]), "r"(a[2]), "r"(a[3]), "r"(b[0]), "r"(b[1]));
}

__device__ __forceinline__ uint2 cvt4(float4 v) {
    __half2 h0 = __floats2half2_rn(v.x, v.y);
    __half2 h1 = __floats2half2_rn(v.z, v.w);
    uint2 pk;
    pk.x = *reinterpret_cast<uint32_t*>(&h0);
    pk.y = *reinterpret_cast<uint32_t*>(&h1);
    return pk;
}

// =====================================================================
// f32 -> f16 conversion kernels
// =====================================================================
__global__ __launch_bounds__(256)
void cvt_f16(const float* __restrict__ in, __half* __restrict__ out, int n4)
{
    const int i = blockIdx.x * blockDim.x + threadIdx.x;
    if (i < n4)
        reinterpret_cast<uint2*>(out)[i] = cvt4(reinterpret_cast<const float4*>(in)[i]);
}

__global__ __launch_bounds__(256)
void cvt_f16x3(const float* __restrict__ s0, __half* __restrict__ d0, int n0,
               const float* __restrict__ s1, __half* __restrict__ d1, int n1,
               const float* __restrict__ s2, __half* __restrict__ d2, int n2)
{
    int i = blockIdx.x * blockDim.x + threadIdx.x;
    if (i < n0) {
        reinterpret_cast<uint2*>(d0)[i] = cvt4(reinterpret_cast<const float4*>(s0)[i]);
        return;
    }
    i -= n0;
    if (i < n1) {
        reinterpret_cast<uint2*>(d1)[i] = cvt4(reinterpret_cast<const float4*>(s1)[i]);
        return;
    }
    i -= n1;
    if (i < n2)
        reinterpret_cast<uint2*>(d2)[i] = cvt4(reinterpret_cast<const float4*>(s2)[i]);
}

// =====================================================================
// fp16 tensor GEMM (TN): C[M,N] = A[M,K]*B[N,K]^T, fp16 in, f32 acc.
// Block 128x128x64, 8 warps (2x4), warp tile 64x32 via m16n8k16.
// 3-stage cp.async pipeline, padded 144B SMEM rows.
// EPI: 0 plain f32, 1 softplus(v+bias[n]). GN guards B rows (N=96).
// SPLITK: blockIdx.z selects K-slice and partial-output slab.
// =====================================================================
constexpr int HROW  = 144;                  // bytes per SMEM row (64 fp16 + 16 pad)
constexpr int HASTG = 128 * HROW;           // 18432 B per operand stage
constexpr int HSTG  = 2 * HASTG;            // 36864 B per stage
constexpr int HSMEM = 3 * HSTG;             // 110592 B

template<int EPI, bool GN, bool SPLITK>
__global__ __launch_bounds__(256, 2)
void h_gemm(const __half* __restrict__ A, int lda,
            const __half* __restrict__ Bw, int ldb,
            float* __restrict__ C, int ldc,
            int K, int N, const float* __restrict__ bias)
{
    extern __shared__ __align__(16) char smraw[];
    const uint32_t sbase = (uint32_t)__cvta_generic_to_shared(smraw);

    if (SPLITK) {
        const size_t kz = (size_t)blockIdx.z;
        A  += kz * K;
        Bw += kz * K;
        C  += kz * (size_t)gridDim.y * 128 * ldc;
    }

    const int tid  = threadIdx.x;
    const int warp = tid >> 5;
    const int lane = tid & 31;
    const int g    = lane >> 2;
    const int t4   = lane & 3;
    const int mw   = (warp >> 2) * 64;
    const int nw   = (warp & 3) * 32;

    const __half* Ab = A  + (size_t)blockIdx.y * 128 * lda;
    const __half* Bb = Bw + (size_t)blockIdx.x * 128 * ldb;
    const int nBase = blockIdx.x * 128;
    const int nt = K / 64;

    const int q  = lane >> 3;
    const int rr = lane & 7;
    const int lmRow = (q & 1) * 8 + rr;
    const int lmCol = (q >> 1) * 16;

    // cp.async: 1024 16B-chunks per operand; 4 per thread (256 threads)
    int cr[4], cc[4];
    #pragma unroll
    for (int u = 0; u < 4; ++u) { int idx = tid + u * 256; cr[u] = idx >> 3; cc[u] = idx & 7; }

    auto loadStage = [&](int t, int s) {
        const int k0 = t * 64;
        const uint32_t aS = sbase + s * HSTG;
        const uint32_t bS = aS + HASTG;
        #pragma unroll
        for (int u = 0; u < 4; ++u) {
            const __half* src = Ab + (size_t)cr[u] * lda + k0 + cc[u] * 8;
            uint32_t dst = aS + (uint32_t)(cr[u] * HROW + cc[u] * 16);
            asm volatile("cp.async.cg.shared.global [%0], [%1], 16;" :: "r"(dst), "l"(src));
        }
        #pragma unroll
        for (int u = 0; u < 4; ++u) {
            uint32_t dst = bS + (uint32_t)(cr[u] * HROW + cc[u] * 16);
            if (GN) {
                const bool ok = (nBase + cr[u]) < N;
                const __half* src = Bb + (size_t)(ok ? cr[u] : 0) * ldb + k0 + cc[u] * 8;
                const int sz = ok ? 16 : 0;
                asm volatile("cp.async.cg.shared.global [%0], [%1], 16, %2;"
                             :: "r"(dst), "l"(src), "r"(sz));
            } else {
                const __half* src = Bb + (size_t)cr[u] * ldb + k0 + cc[u] * 8;
                asm volatile("cp.async.cg.shared.global [%0], [%1], 16;" :: "r"(dst), "l"(src));
            }
        }
    };

    float acc[4][4][4];
    #pragma unroll
    for (int i = 0; i < 4; ++i)
        #pragma unroll
        for (int j = 0; j < 4; ++j)
            #pragma unroll
            for (int r = 0; r < 4; ++r) acc[i][j][r] = 0.f;

    // prologue: 2 committed groups (3-stage pipeline)
    #pragma unroll
    for (int t = 0; t < 2; ++t) {
        if (t < nt) loadStage(t, t);
        asm volatile("cp.async.commit_group;");
    }

    for (int t = 0; t < nt; ++t) {
        asm volatile("cp.async.wait_group 1;");
        __syncthreads();
        if (t + 2 < nt) loadStage(t + 2, (t + 2) % 3);
        asm volatile("cp.async.commit_group;");

        const int s = t % 3;
        const uint32_t aS = sbase + s * HSTG;
        const uint32_t bS = aS + HASTG;

        #pragma unroll
        for (int kk = 0; kk < 4; ++kk) {
            uint32_t af[4][4], bf[4][2];
            #pragma unroll
            for (int i = 0; i < 4; ++i) {
                const uint32_t ad = aS + (uint32_t)((mw + i * 16 + lmRow) * HROW + kk * 32 + lmCol);
                asm volatile("ldmatrix.sync.aligned.m8n8.x4.shared.b16 {%0,%1,%2,%3}, [%4];"
                    : "=r"(af[i][0]), "=r"(af[i][1]), "=r"(af[i][2]), "=r"(af[i][3])
                    : "r"(ad));
            }
            #pragma unroll
            for (int jj = 0; jj < 2; ++jj) {
                const uint32_t bd = bS + (uint32_t)((nw + jj * 16 + lmRow) * HROW + kk * 32 + lmCol);
                asm volatile("ldmatrix.sync.aligned.m8n8.x4.shared.b16 {%0,%1,%2,%3}, [%4];"
                    : "=r"(bf[2*jj][0]), "=r"(bf[2*jj+1][0]), "=r"(bf[2*jj][1]), "=r"(bf[2*jj+1][1])
                    : "r"(bd));
            }
            #pragma unroll
            for (int i = 0; i < 4; ++i)
                #pragma unroll
                for (int j = 0; j < 4; ++j)
                    mma_f16(acc[i][j], af[i], bf[j]);
        }
    }

    // ---- epilogue ----
    #pragma unroll
    for (int i = 0; i < 4; ++i) {
        const int m = blockIdx.y * 128 + mw + i * 16 + g;
        #pragma unroll
        for (int j = 0; j < 4; ++j) {
            const int n = nBase + nw + j * 8 + t4 * 2;
            if (GN && n + 2 > N) continue;
            float v0 = acc[i][j][0], v1 = acc[i][j][1];
            float v2 = acc[i][j][2], v3 = acc[i][j][3];
            if (EPI == 1) {
                const float b0v = bias[n], b1v = bias[n + 1];
                v0 += b0v; v1 += b1v; v2 += b0v; v3 += b1v;
                v0 = (v0 > 20.f) ? v0 : log1pf(__expf(v0));
                v1 = (v1 > 20.f) ? v1 : log1pf(__expf(v1));
                v2 = (v2 > 20.f) ? v2 : log1pf(__expf(v2));
                v3 = (v3 > 20.f) ? v3 : log1pf(__expf(v3));
            }
            *reinterpret_cast<float2*>(&C[(size_t)m * ldc + n])       = make_float2(v0, v1);
            *reinterpret_cast<float2*>(&C[(size_t)(m + 8) * ldc + n]) = make_float2(v2, v3);
        }
    }
}

// =====================================================================
// split-K reduction for x_dbl: sums KSPL partials -> f32 + fp16
// =====================================================================
__global__ __launch_bounds__(256)
void reduce_xdbl(int n4)
{
    const int i = blockIdx.x * blockDim.x + threadIdx.x;
    if (i >= n4) return;
    const size_t stride4 = (size_t)BATCH * L * XD / 4;
    const float4* p = reinterpret_cast<const float4*>(g_xdbl_p);
    float4 a = p[i], b = p[i + stride4], c = p[i + 2 * stride4], d = p[i + 3 * stride4];
    float4 s;
    s.x = (a.x + b.x) + (c.x + d.x);
    s.y = (a.y + b.y) + (c.y + d.y);
    s.z = (a.z + b.z) + (c.z + d.z);
    s.w = (a.w + b.w) + (c.w + d.w);
    reinterpret_cast<float4*>(g_xdbl)[i] = s;
    reinterpret_cast<uint2*>(g_xdblh)[i] = cvt4(s);
}

// =====================================================================
// Dual dilated causal depthwise conv + silu + softmax gate.
// =====================================================================
__global__ __launch_bounds__(256)
void conv_kernel(const float* __restrict__ w1, const float* __restrict__ b1,
                 const float* __restrict__ w2, const float* __restrict__ b2,
                 const float* __restrict__ gates)
{
    const int tid = blockIdx.x * blockDim.x + threadIdx.x;
    const int d    = tid % DI;
    const int rest = tid / DI;
    const int lc   = rest % (L / 16);
    const int b    = rest / (L / 16);
    const int l0   = lc * 16;

    const float* xp = g_xz + (size_t)b * L * E2 + d;
    const size_t obase = (size_t)b * L * DI + d;

    const float w10 = w1[d*4+0], w11 = w1[d*4+1], w12 = w1[d*4+2], w13 = w1[d*4+3];
    const float w20 = w2[d*4+0], w21 = w2[d*4+1], w22 = w2[d*4+2], w23 = w2[d*4+3];
    const float b1v = b1[d], b2v = b2[d];
    const float e0 = __expf(gates[0]), e1 = __expf(gates[1]);
    const float gden = 1.f / (e0 + e1);
    const float g0 = e0 * gden, g1 = e1 * gden;

    float xb[22];
    #pragma unroll
    for (int i = 0; i < 22; ++i) {
        const int l = l0 - 6 + i;
        xb[i] = (l >= 0) ? xp[(size_t)l * E2] : 0.f;
    }
    #pragma unroll
    for (int i = 0; i < 16; ++i) {
        const float x0  = xb[i+6], xm1 = xb[i+5], xm2 = xb[i+4];
        const float xm3 = xb[i+3], xm4 = xb[i+2], xm6 = xb[i+0];
        const float c1 = fmaf(w13, x0, fmaf(w12, xm1, fmaf(w11, xm2, fmaf(w10, xm3, b1v))));
        const float c2 = fmaf(w23, x0, fmaf(w22, xm2, fmaf(w21, xm4, fmaf(w20, xm6, b2v))));
        const float s1 = c1 * sigmoidf_(c1);
        const float s2 = c2 * sigmoidf_(c2);
        const float v  = fmaf(g0, s1, g1 * s2);
        g_xc  [obase + (size_t)(l0 + i) * DI] = v;
        g_xc_h[obase + (size_t)(l0 + i) * DI] = __float2half_rn(v);
    }
}

// =====================================================================
// Selective scan + D-skip + silu(z) gate, SMEM-staged operands.
// NEW LAYOUT: 8 lanes per channel, 2 states per lane (n and n+8).
// Warp = 4 channels; block = 256 threads = 8 warps = 32 channels.
// B/C staged once per block (shared across channels).
// Double-buffered 16-timestep chunks, coalesced float2 staging.
// =====================================================================
constexpr int CH  = 16;   // timesteps per chunk
constexpr int CPB = 32;   // channels per block
__global__ __launch_bounds__(256)
void scan_kernel(const float* __restrict__ A_log, const float* __restrict__ D_param)
{
    __shared__ float sd [2][CH][CPB];   // delta
    __shared__ float sxv[2][CH][CPB];   // xc
    __shared__ float szv[2][CH][CPB];   // z
    __shared__ float sbc[2][CH][32];    // B(16) | C(16), channel-independent

    const int tid   = threadIdx.x;
    const int warp  = tid >> 5;
    const int lane  = tid & 31;
    const int grp   = lane >> 3;         // channel-in-warp (0..3)
    const int n     = lane & 7;          // state base (pairs n, n+8)
    const int ch    = warp * 4 + grp;    // channel within block (0..31)
    const int blk   = blockIdx.x;        // BATCH * (DI/CPB) = 256
    const int b     = blk >> 6;          // / (DI/CPB=64)
    const int dbase = (blk & 63) * CPB;
    const int d     = dbase + ch;

    const float LG2E = 1.4426950408889634f;
    const float Ac0 = -__expf(A_log[d * DS + n])     * LG2E;
    const float Ac1 = -__expf(A_log[d * DS + n + 8]) * LG2E;
    const float Dv  = D_param[d];

    // staging: thread -> (srow = timestep-in-chunk, sc2 = channel pair)
    const int srow = tid >> 4;           // 0..15
    const int sc2  = (tid & 15) * 2;     // 0,2,..,30
    const size_t mb = (size_t)b * L;     // row base (b,l)

    auto stage = [&](int c, int buf) {
        const int l = c * CH + srow;
        float2 t;
        t = *reinterpret_cast<const float2*>(g_delta + (mb + l) * DI + dbase + sc2);
        sd [buf][srow][sc2] = t.x; sd [buf][srow][sc2 + 1] = t.y;
        t = *reinterpret_cast<const float2*>(g_xc + (mb + l) * DI + dbase + sc2);
        sxv[buf][srow][sc2] = t.x; sxv[buf][srow][sc2 + 1] = t.y;
        t = *reinterpret_cast<const float2*>(g_xz + (mb + l) * E2 + DI + dbase + sc2);
        szv[buf][srow][sc2] = t.x; szv[buf][srow][sc2 + 1] = t.y;
        t = *reinterpret_cast<const float2*>(g_xdbl + (mb + l) * XD + DR + sc2);
        sbc[buf][srow][sc2] = t.x; sbc[buf][srow][sc2 + 1] = t.y;
    };

    stage(0, 0);
    __syncthreads();

    __half* yp = g_y_h + mb * DI + d;
    float h0 = 0.f, h1 = 0.f;

    for (int c = 0; c < L / CH; ++c) {
        const int buf = c & 1;
        if (c + 1 < L / CH) stage(c + 1, buf ^ 1);

        const int lbase = c * CH;
        #pragma unroll
        for (int i = 0; i < CH; ++i) {
            const float dlt = sd [buf][i][ch];
            const float xv  = sxv[buf][i][ch];
            const float zv  = szv[buf][i][ch];
            const float B0  = sbc[buf][i][n];
            const float B1  = sbc[buf][i][n + 8];
            const float C0  = sbc[buf][i][16 + n];
            const float C1  = sbc[buf][i][24 + n];

            const float dA0 = ex2_(dlt * Ac0);
            const float dA1 = ex2_(dlt * Ac1);
            const float tt  = dlt * xv;
            h0 = fmaf(h0, dA0, tt * B0);
            h1 = fmaf(h1, dA1, tt * B1);

            float v = fmaf(h1, C1, h0 * C0);
            v += __shfl_xor_sync(FULLMASK, v, 1);
            v += __shfl_xor_sync(FULLMASK, v, 2);
            v += __shfl_xor_sync(FULLMASK, v, 4);

            if (n == 0) {
                const float y = fmaf(Dv, xv, v);
                yp[(size_t)(lbase + i) * DI] = __float2half_rn(y * (zv * sigmoidf_(zv)));
            }
        }
        __syncthreads();
    }
}

// =====================================================================
extern "C" void kernel_launch(void* const* d_in, const int* in_sizes, int n_in,
                              void* d_out, int out_size)
{
    const float* hidden     = (const float*)d_in[0];
    const float* W_in       = (const float*)d_in[1];
    const float* conv_w1    = (const float*)d_in[2];
    const float* conv_b1    = (const float*)d_in[3];
    const float* conv_w2    = (const float*)d_in[4];
    const float* conv_b2    = (const float*)d_in[5];
    const float* conv_gates = (const float*)d_in[6];
    const float* W_x        = (const float*)d_in[7];
    const float* W_dt       = (const float*)d_in[8];
    const float* b_dt       = (const float*)d_in[9];
    const float* A_log      = (const float*)d_in[10];
    const float* D_param    = (const float*)d_in[11];
    const float* W_out      = (const float*)d_in[12];
    float*       out        = (float*)d_out;

    float  *p_xz, *p_xdbl_p, *p_delta;
    __half *p_xch, *p_xdblh, *p_yh, *p_h, *p_win, *p_wx, *p_wdt, *p_wout;
    cudaGetSymbolAddress((void**)&p_xz,     g_xz);
    cudaGetSymbolAddress((void**)&p_xdbl_p, g_xdbl_p);
    cudaGetSymbolAddress((void**)&p_delta,  g_delta);
    cudaGetSymbolAddress((void**)&p_xch,    g_xc_h);
    cudaGetSymbolAddress((void**)&p_xdblh,  g_xdblh);
    cudaGetSymbolAddress((void**)&p_yh,     g_y_h);
    cudaGetSymbolAddress((void**)&p_h,      g_h_h);
    cudaGetSymbolAddress((void**)&p_win,    g_win_h);
    cudaGetSymbolAddress((void**)&p_wx,     g_wx_h);
    cudaGetSymbolAddress((void**)&p_wdt,    g_wdt_h);
    cudaGetSymbolAddress((void**)&p_wout,   g_wout_h);

    static bool attr_done = false;
    if (!attr_done) {
        cudaFuncSetAttribute((const void*)h_gemm<0,false,false>,
                             cudaFuncAttributeMaxDynamicSharedMemorySize, HSMEM);
        cudaFuncSetAttribute((const void*)h_gemm<1,false,false>,
                             cudaFuncAttributeMaxDynamicSharedMemorySize, HSMEM);
        cudaFuncSetAttribute((const void*)h_gemm<0,true,true>,
                             cudaFuncAttributeMaxDynamicSharedMemorySize, HSMEM);
        attr_done = true;
    }

    const int M = BATCH * L;   // 8192

    // [0] cvt hidden, [1] cvt W_in, [2] fused cvt of W_out/W_x/W_dt
    {
        int n4h = (int)((size_t)BATCH * L * DM / 4);
        cvt_f16<<<(n4h + 255) / 256, 256>>>(hidden, p_h, n4h);
        int n4w = (int)((size_t)E2 * DM / 4);
        cvt_f16<<<(n4w + 255) / 256, 256>>>(W_in, p_win, n4w);
        int n0 = (int)((size_t)DM * DI / 4);
        int n1 = (int)((size_t)XD * DI / 4);
        int n2 = (int)((size_t)DI * DR / 4);
        cvt_f16x3<<<(n0 + n1 + n2 + 255) / 256, 256>>>(
            W_out, p_wout, n0, W_x, p_wx, n1, W_dt, p_wdt, n2);
    }

    // [3] in-proj: (M=8192, N=4096, K=1024)
    h_gemm<0,false,false><<<dim3(E2/128, M/128), 256, HSMEM>>>(
        p_h, DM, p_win, DM, p_xz, E2, DM, E2, nullptr);

    // [4] dwconv + silu + gate -> g_xc (f32) + g_xc_h (fp16)
    conv_kernel<<<(BATCH * (L/16) * DI) / 256, 256>>>(
        conv_w1, conv_b1, conv_w2, conv_b2, conv_gates);

    // [5] x_dbl split-K: (M=8192, N=96, K=2048/4 per slice)
    h_gemm<0,true,true><<<dim3(1, M/128, KSPL), 256, HSMEM>>>(
        p_xch, DI, p_wx, DI, p_xdbl_p, XD, DI / KSPL, XD, nullptr);

    // [6] reduce partials -> g_xdbl (f32) + g_xdblh (fp16)
    {
        int n4 = (int)((size_t)BATCH * L * XD / 4);
        reduce_xdbl<<<(n4 + 255) / 256, 256>>>(n4);
    }

    // [7] delta = softplus(dt_low . W_dt^T + b_dt): (M=8192, N=2048, K=64)
    h_gemm<1,false,false><<<dim3(DI/128, M/128), 256, HSMEM>>>(
        p_xdblh, XD, p_wdt, DR, p_delta, DI, DR, DI, b_dt);

    // [8] selective scan -> g_y_h (fp16)
    scan_kernel<<<BATCH * (DI / CPB), 256>>>(A_log, D_param);

    // [9] out-proj: (M=8192, N=1024, K=2048)
    h_gemm<0,false,false><<<dim3(DM/128, M/128), 256, HSMEM>>>(
        p_yh, DI, p_wout, DI, out, DM, DI, DM, nullptr);
}